// round 13
// baseline (speedup 1.0000x reference)
#include <cuda_runtime.h>
#include <cuda_fp16.h>
#include <cstdint>
#include <cstddef>

// Problem constants
#define D_MODEL 2048
#define SEQ     2048
#define PAST    2048
#define NHEAD   16
#define HDIM    128
#define BATCH   2
#define MROWS   (BATCH*SEQ)     // 4096
#define KVTOT   (PAST+SEQ)      // 4096
#define NQT     (SEQ/64)        // 32 q-tiles per (b,h)

// Scratch (device globals — allocation-free per harness rules)
__device__ __half g_xh [MROWS*D_MODEL];               // fp16 x
__device__ __half g_q  [MROWS*D_MODEL];
__device__ __half g_k  [MROWS*D_MODEL];
__device__ __half g_v  [MROWS*D_MODEL];
__device__ __half g_att[MROWS*D_MODEL];
__device__ __half g_ck [BATCH*PAST*D_MODEL];          // fp16 cache_k (natural)
__device__ __half g_cv [BATCH*PAST*D_MODEL];          // fp16 cache_v (natural)
__device__ __half g_wt [4*(size_t)D_MODEL*D_MODEL];   // transposed fp16 weights (q,k,v,o)
// split-KV partials: [kvh][b][h][qt][64 rows][128 cols]
__device__ __half g_po [2*BATCH*NHEAD*NQT*64*128];    // 67 MB
__device__ float  g_pm [2*BATCH*NHEAD*NQT*64];
__device__ float  g_pl [2*BATCH*NHEAD*NQT*64];

// ---------------------------------------------------------------------------
// helpers
// ---------------------------------------------------------------------------
__device__ __forceinline__ uint32_t smem_u32(const void* p) {
    uint32_t a;
    asm("{ .reg .u64 t; cvta.to.shared.u64 t, %1; cvt.u32.u64 %0, t; }" : "=r"(a) : "l"(p));
    return a;
}
__device__ __forceinline__ void cp_async16(uint32_t sdst, const void* gsrc) {
    asm volatile("cp.async.cg.shared.global [%0], [%1], 16;" :: "r"(sdst), "l"(gsrc));
}
__device__ __forceinline__ void cp_commit() {
    asm volatile("cp.async.commit_group;");
}
template<int N>
__device__ __forceinline__ void cp_wait() {
    asm volatile("cp.async.wait_group %0;" :: "n"(N));
}
__device__ __forceinline__ void mma_h(float& c0, float& c1, float& c2, float& c3,
                                      uint32_t a0, uint32_t a1, uint32_t a2, uint32_t a3,
                                      uint32_t b0, uint32_t b1) {
    asm volatile("mma.sync.aligned.m16n8k16.row.col.f32.f16.f16.f32 "
                 "{%0,%1,%2,%3}, {%4,%5,%6,%7}, {%8,%9}, {%0,%1,%2,%3};"
                 : "+f"(c0), "+f"(c1), "+f"(c2), "+f"(c3)
                 : "r"(a0), "r"(a1), "r"(a2), "r"(a3), "r"(b0), "r"(b1));
}
__device__ __forceinline__ void ldsm_x4(uint32_t& r0, uint32_t& r1, uint32_t& r2, uint32_t& r3,
                                        uint32_t addr) {
    asm volatile("ldmatrix.sync.aligned.m8n8.x4.shared.b16 {%0,%1,%2,%3}, [%4];"
                 : "=r"(r0), "=r"(r1), "=r"(r2), "=r"(r3) : "r"(addr));
}
__device__ __forceinline__ void ldsm_x4_t(uint32_t& r0, uint32_t& r1, uint32_t& r2, uint32_t& r3,
                                          uint32_t addr) {
    asm volatile("ldmatrix.sync.aligned.m8n8.x4.trans.shared.b16 {%0,%1,%2,%3}, [%4];"
                 : "=r"(r0), "=r"(r1), "=r"(r2), "=r"(r3) : "r"(addr));
}

// ---------------------------------------------------------------------------
// fp16 GEMM core (R7 config: CTA 128x256, BK=64, 8 warps/256thr, warp 64x64,
// 3-stage cp.async pipeline).
// ---------------------------------------------------------------------------
#define GBM 128
#define GBN 256
#define GBK 64
#define SWH 72
#define AS_H (GBM*SWH)
#define BS_H (GBN*SWH)
#define STG_H (AS_H+BS_H)
#define GSTG 3
#define GEMM_DSMEM (GSTG*STG_H*2)   // 165888
#define NCHUNK (D_MODEL/GBK)        // 32

struct GemmCore {
    __device__ static void run(const __half* A, const __half* Bt,
                               const float* bias, void* Cout, int half_out,
                               int m0, int n0glob, int ncol0, __half* sh)
    {
        const uint32_t sbase = smem_u32(sh);
        const int tid  = threadIdx.x;
        const int wid  = tid >> 5;
        const int lane = tid & 31;
        const int r    = lane >> 2;
        const int cc   = lane & 3;
        const int wm = (wid >> 2) * 64;
        const int wn = (wid & 3) * 64;

        const int row8 = tid >> 3;
        const int seg  = tid & 7;
        const __half* Ag = A  + (size_t)(m0 + row8) * D_MODEL + seg * 8;
        const __half* Bg = Bt + (size_t)(n0glob + row8) * D_MODEL + seg * 8;

        float c[4][8][4];
        #pragma unroll
        for (int mi = 0; mi < 4; mi++)
            #pragma unroll
            for (int ni = 0; ni < 8; ni++)
                #pragma unroll
                for (int j = 0; j < 4; j++) c[mi][ni][j] = 0.f;

        auto load_chunk = [&](int chunk, int st) {
            uint32_t as = sbase + (st*STG_H) * 2;
            uint32_t bs = as + AS_H * 2;
            const __half* ag = Ag + chunk * GBK;
            const __half* bg = Bg + chunk * GBK;
            #pragma unroll
            for (int i = 0; i < 4; i++) {
                int row = row8 + i * 32;
                cp_async16(as + (uint32_t)(row*SWH + seg*8)*2, ag + (size_t)i*32*D_MODEL);
            }
            #pragma unroll
            for (int i = 0; i < 8; i++) {
                int row = row8 + i * 32;
                cp_async16(bs + (uint32_t)(row*SWH + seg*8)*2, bg + (size_t)i*32*D_MODEL);
            }
            cp_commit();
        };

        load_chunk(0, 0);
        load_chunk(1, 1);
        load_chunk(2, 2);

        for (int ch = 0; ch < NCHUNK; ch++) {
            int rem = NCHUNK - 1 - ch;
            if (rem >= 2)      cp_wait<2>();
            else if (rem == 1) cp_wait<1>();
            else               cp_wait<0>();
            __syncthreads();

            int st = ch % GSTG;
            const uint32_t* As32 = (const uint32_t*)(sh + st * STG_H);
            const uint32_t* Bs32 = As32 + AS_H/2;
            const uint32_t* pA = As32 + (wm + r) * (SWH/2) + cc;
            const uint32_t* pB = Bs32 + (wn + r) * (SWH/2) + cc;

            #pragma unroll
            for (int ks = 0; ks < 4; ks++) {
                uint32_t a[4][4];
                #pragma unroll
                for (int mi = 0; mi < 4; mi++) {
                    const uint32_t* p = pA + mi*16*(SWH/2) + ks*8;
                    a[mi][0] = p[0];
                    a[mi][1] = p[8*(SWH/2)];
                    a[mi][2] = p[4];
                    a[mi][3] = p[8*(SWH/2) + 4];
                }
                uint32_t b[8][2];
                #pragma unroll
                for (int ni = 0; ni < 8; ni++) {
                    const uint32_t* p = pB + ni*8*(SWH/2) + ks*8;
                    b[ni][0] = p[0];
                    b[ni][1] = p[4];
                }
                #pragma unroll
                for (int mi = 0; mi < 4; mi++)
                    #pragma unroll
                    for (int ni = 0; ni < 8; ni++)
                        mma_h(c[mi][ni][0], c[mi][ni][1], c[mi][ni][2], c[mi][ni][3],
                              a[mi][0], a[mi][1], a[mi][2], a[mi][3],
                              b[ni][0], b[ni][1]);
            }
            __syncthreads();
            if (ch + GSTG < NCHUNK) load_chunk(ch + GSTG, st);
        }

        #pragma unroll
        for (int mi = 0; mi < 4; mi++) {
            int row = m0 + wm + mi*16 + r;
            #pragma unroll
            for (int ni = 0; ni < 8; ni++) {
                int col = ncol0 + wn + ni*8 + cc*2;
                float2 bv = *(const float2*)(bias + col);
                float o00 = c[mi][ni][0] + bv.x, o01 = c[mi][ni][1] + bv.y;
                float o10 = c[mi][ni][2] + bv.x, o11 = c[mi][ni][3] + bv.y;
                if (half_out) {
                    __half* Ch = (__half*)Cout;
                    *(__half2*)(Ch + (size_t)row*D_MODEL + col)     = __floats2half2_rn(o00, o01);
                    *(__half2*)(Ch + (size_t)(row+8)*D_MODEL + col) = __floats2half2_rn(o10, o11);
                } else {
                    float* Cf = (float*)Cout;
                    *(float2*)(Cf + (size_t)row*D_MODEL + col)     = make_float2(o00, o01);
                    *(float2*)(Cf + (size_t)(row+8)*D_MODEL + col) = make_float2(o10, o11);
                }
            }
        }
    }
};

// fused QKV: Bt rows 0..6143 = wq^T | wk^T | wv^T
__global__ __launch_bounds__(256, 1)
void gemm_qkv(const __half* __restrict__ A, const __half* __restrict__ BtAll,
              const float* __restrict__ bq, const float* __restrict__ bk,
              const float* __restrict__ bv,
              __half* __restrict__ Cq, __half* __restrict__ Ck, __half* __restrict__ Cv)
{
    extern __shared__ __half sh[];
    int n0g = blockIdx.x * GBN;
    int mat = n0g >> 11;
    const float* bias = (mat == 0) ? bq : (mat == 1) ? bk : bv;
    __half* C = (mat == 0) ? Cq : (mat == 1) ? Ck : Cv;
    GemmCore::run(A, BtAll, bias, C, 1, blockIdx.y * GBM, n0g, n0g & 2047, sh);
}

__global__ __launch_bounds__(256, 1)
void gemm_o(const __half* __restrict__ A, const __half* __restrict__ Bt,
            const float* __restrict__ bias, float* __restrict__ C)
{
    extern __shared__ __half sh[];
    int n0 = blockIdx.x * GBN;
    GemmCore::run(A, Bt, bias, C, 0, blockIdx.y * GBM, n0, n0, sh);
}

// ---------------------------------------------------------------------------
// Prep (critical path only): y=0..2 convert x/ck/cv; y=3..5 transpose wq,wk,wv.
// (wo transpose rides in the combine kernel — only gemm_o needs it.)
// ---------------------------------------------------------------------------
__global__ __launch_bounds__(256, 4)
void prep_all(const float* __restrict__ x, const float* __restrict__ ck,
              const float* __restrict__ cv,
              const float* __restrict__ wq, const float* __restrict__ wk,
              const float* __restrict__ wv,
              __half* __restrict__ dx, __half* __restrict__ dck,
              __half* __restrict__ dcv, __half* __restrict__ dw)
{
    __shared__ float t[32][33];
    int y = blockIdx.y;
    if (y < 3) {
        const float* src = (y == 0) ? x : (y == 1) ? ck : cv;
        __half* dst = (y == 0) ? dx : (y == 1) ? dck : dcv;
        int i = (blockIdx.x * blockDim.x + threadIdx.x) * 8;
        float4 f0 = *(const float4*)(src + i);
        float4 f1 = *(const float4*)(src + i + 4);
        __half2 h[4];
        h[0] = __floats2half2_rn(f0.x, f0.y);
        h[1] = __floats2half2_rn(f0.z, f0.w);
        h[2] = __floats2half2_rn(f1.x, f1.y);
        h[3] = __floats2half2_rn(f1.z, f1.w);
        *(uint4*)(dst + i) = *(const uint4*)h;
    } else {
        int z = y - 3;
        const float* src = (z == 0) ? wq : (z == 1) ? wk : wv;
        __half* dst = dw + (size_t)z * D_MODEL * D_MODEL;
        int bx = (blockIdx.x & 63) * 32, by = (blockIdx.x >> 6) * 32;
        int tx = threadIdx.x & 31, ty = threadIdx.x >> 5;  // 32 x 8
        int xcol = bx + tx;
        #pragma unroll
        for (int i = 0; i < 32; i += 8)
            t[ty + i][tx] = src[(size_t)(by + ty + i) * D_MODEL + xcol];
        __syncthreads();
        xcol = by + tx;
        #pragma unroll
        for (int i = 0; i < 32; i += 8)
            dst[(size_t)(bx + ty + i) * D_MODEL + xcol] = __float2half(t[tx][ty + i]);
    }
}

// ---------------------------------------------------------------------------
// fp16 flash attention, split-KV (R7/R11 structure: 128 thr, occ 2, partials)
// ---------------------------------------------------------------------------
#define QT 64
#define KT 64
#define NTH (KVTOT/KT/2)       // 32 tiles per half
#define SQH 136
#define OFF_Q      0
#define OFF_K(st)  (8704 + (st)*8704)
#define OFF_V(st)  (26112 + (st)*8704)
#define ATTN_SMEM_H ((26112 + 2*8704)*2)   // 87040 bytes

__global__ __launch_bounds__(128, 2)
void attn_h(void)
{
    extern __shared__ __half sm[];
    const uint32_t sbase = smem_u32(sm);
    const int tid  = threadIdx.x;
    const int wid  = tid >> 5;
    const int lane = tid & 31;
    const int r    = lane >> 2;
    const int cc   = lane & 3;
    const int kvh  = blockIdx.x >> 5;
    const int qt   = blockIdx.x & (NQT-1);
    const int h  = blockIdx.y;
    const int b  = blockIdx.z;
    const int q0 = qt * QT;
    const int t0 = kvh * NTH;

    {
        const __half* qg = g_q + ((size_t)(b*SEQ + q0))*D_MODEL + h*HDIM;
        #pragma unroll
        for (int i = 0; i < 8; i++) {
            int s = tid + i*128;
            int row = s >> 4, seg = s & 15;
            cp_async16(sbase + (uint32_t)(OFF_Q + row*SQH + seg*8)*2,
                       qg + (size_t)row*D_MODEL + seg*8);
        }
        cp_commit();
    }

    auto load_tile = [&](int t, int st) {
        int kv0 = t * KT;
        const __half *kb, *vb;
        if (kv0 < PAST) {
            size_t off = ((size_t)(b*PAST + kv0))*D_MODEL + h*HDIM;
            kb = g_ck + off; vb = g_cv + off;
        } else {
            size_t off = ((size_t)(b*SEQ + (kv0-PAST)))*D_MODEL + h*HDIM;
            kb = g_k + off; vb = g_v + off;
        }
        #pragma unroll
        for (int i = 0; i < 8; i++) {
            int s = tid + i*128;
            int row = s >> 4, seg = s & 15;
            cp_async16(sbase + (uint32_t)(OFF_K(st) + row*SQH + seg*8)*2,
                       kb + (size_t)row*D_MODEL + seg*8);
            cp_async16(sbase + (uint32_t)(OFF_V(st) + row*SQH + seg*8)*2,
                       vb + (size_t)row*D_MODEL + seg*8);
        }
        cp_commit();
    };

    load_tile(t0, 0);
    load_tile(t0 + 1, 1);
    cp_wait<1>();
    __syncthreads();

    uint32_t qa[8][4];
    {
        int g  = lane >> 3, kr = lane & 7;
        int qrow = wid*16 + (g & 1)*8 + kr;
        int cbase = (g >> 1)*8;
        #pragma unroll
        for (int kb = 0; kb < 8; kb++) {
            uint32_t addr = sbase + (uint32_t)(OFF_Q + qrow*SQH + kb*16 + cbase)*2;
            ldsm_x4(qa[kb][0], qa[kb][1], qa[kb][2], qa[kb][3], addr);
        }
    }

    float o[16][4];
    #pragma unroll
    for (int nj = 0; nj < 16; nj++)
        #pragma unroll
        for (int j = 0; j < 4; j++) o[nj][j] = 0.f;
    float m0 = -1e30f, m1 = -1e30f, l0 = 0.f, l1 = 0.f;

    const float sc = 0.08838834764831845f;

    const int kg = lane >> 3, kkr = lane & 7;
    const int k_row_off = (kg >> 1)*8 + kkr;
    const int k_col_off = (kg & 1)*8;
    const int v_row_off = lane & 15;
    const int v_col_off = (lane >> 4)*8;

    for (int lt = 0; lt < NTH; lt++) {
        const uint32_t kbase = sbase + (uint32_t)OFF_K(lt & 1)*2;
        const uint32_t vbase = sbase + (uint32_t)OFF_V(lt & 1)*2;

        float s[8][4];
        #pragma unroll
        for (int ni = 0; ni < 8; ni++)
            #pragma unroll
            for (int j = 0; j < 4; j++) s[ni][j] = 0.f;

        #pragma unroll
        for (int np = 0; np < 4; np++) {
            #pragma unroll
            for (int kb = 0; kb < 8; kb++) {
                uint32_t b0, b1, b2, b3;
                uint32_t addr = kbase + (uint32_t)((np*16 + k_row_off)*SQH + kb*16 + k_col_off)*2;
                ldsm_x4(b0, b1, b2, b3, addr);
                mma_h(s[2*np][0], s[2*np][1], s[2*np][2], s[2*np][3],
                      qa[kb][0], qa[kb][1], qa[kb][2], qa[kb][3], b0, b1);
                mma_h(s[2*np+1][0], s[2*np+1][1], s[2*np+1][2], s[2*np+1][3],
                      qa[kb][0], qa[kb][1], qa[kb][2], qa[kb][3], b2, b3);
            }
        }

        float mx0 = -1e30f, mx1 = -1e30f;
        #pragma unroll
        for (int ni = 0; ni < 8; ni++) {
            s[ni][0] *= sc; s[ni][1] *= sc; s[ni][2] *= sc; s[ni][3] *= sc;
            mx0 = fmaxf(mx0, fmaxf(s[ni][0], s[ni][1]));
            mx1 = fmaxf(mx1, fmaxf(s[ni][2], s[ni][3]));
        }
        mx0 = fmaxf(mx0, __shfl_xor_sync(0xffffffffu, mx0, 1));
        mx0 = fmaxf(mx0, __shfl_xor_sync(0xffffffffu, mx0, 2));
        mx1 = fmaxf(mx1, __shfl_xor_sync(0xffffffffu, mx1, 1));
        mx1 = fmaxf(mx1, __shfl_xor_sync(0xffffffffu, mx1, 2));

        float nm0 = fmaxf(m0, mx0), nm1 = fmaxf(m1, mx1);
        float al0 = __expf(m0 - nm0), al1 = __expf(m1 - nm1);
        float sum0 = 0.f, sum1 = 0.f;
        #pragma unroll
        for (int ni = 0; ni < 8; ni++) {
            s[ni][0] = __expf(s[ni][0] - nm0);
            s[ni][1] = __expf(s[ni][1] - nm0);
            s[ni][2] = __expf(s[ni][2] - nm1);
            s[ni][3] = __expf(s[ni][3] - nm1);
            sum0 += s[ni][0] + s[ni][1];
            sum1 += s[ni][2] + s[ni][3];
        }
        sum0 += __shfl_xor_sync(0xffffffffu, sum0, 1);
        sum0 += __shfl_xor_sync(0xffffffffu, sum0, 2);
        sum1 += __shfl_xor_sync(0xffffffffu, sum1, 1);
        sum1 += __shfl_xor_sync(0xffffffffu, sum1, 2);
        l0 = l0*al0 + sum0;  m0 = nm0;
        l1 = l1*al1 + sum1;  m1 = nm1;

        #pragma unroll
        for (int nj = 0; nj < 16; nj++) {
            o[nj][0] *= al0; o[nj][1] *= al0;
            o[nj][2] *= al1; o[nj][3] *= al1;
        }

        uint32_t pa[4][4];
        #pragma unroll
        for (int ks = 0; ks < 4; ks++) {
            __half2 h00 = __floats2half2_rn(s[2*ks][0],   s[2*ks][1]);
            __half2 h01 = __floats2half2_rn(s[2*ks][2],   s[2*ks][3]);
            __half2 h10 = __floats2half2_rn(s[2*ks+1][0], s[2*ks+1][1]);
            __half2 h11 = __floats2half2_rn(s[2*ks+1][2], s[2*ks+1][3]);
            pa[ks][0] = *(uint32_t*)&h00;
            pa[ks][1] = *(uint32_t*)&h01;
            pa[ks][2] = *(uint32_t*)&h10;
            pa[ks][3] = *(uint32_t*)&h11;
        }

        #pragma unroll
        for (int np = 0; np < 8; np++) {
            #pragma unroll
            for (int ks = 0; ks < 4; ks++) {
                uint32_t v0, v1, v2, v3;
                uint32_t addr = vbase + (uint32_t)((ks*16 + v_row_off)*SQH + np*16 + v_col_off)*2;
                ldsm_x4_t(v0, v1, v2, v3, addr);
                mma_h(o[2*np][0], o[2*np][1], o[2*np][2], o[2*np][3],
                      pa[ks][0], pa[ks][1], pa[ks][2], pa[ks][3], v0, v1);
                mma_h(o[2*np+1][0], o[2*np+1][1], o[2*np+1][2], o[2*np+1][3],
                      pa[ks][0], pa[ks][1], pa[ks][2], pa[ks][3], v2, v3);
            }
        }

        __syncthreads();
        if (lt + 1 < NTH) {
            if (lt + 2 < NTH) { load_tile(t0 + lt + 2, lt & 1); cp_wait<1>(); }
            else              cp_wait<0>();
            __syncthreads();
        }
    }

    const int u = ((kvh*BATCH + b)*NHEAD + h)*NQT + qt;
    __half* po = g_po + (size_t)u * (QT*HDIM);
    const int row0 = wid*16 + r;
    #pragma unroll
    for (int nj = 0; nj < 16; nj++) {
        __half2 h0 = __floats2half2_rn(o[nj][0], o[nj][1]);
        __half2 h1 = __floats2half2_rn(o[nj][2], o[nj][3]);
        *(__half2*)(po + row0*HDIM     + nj*8 + 2*cc) = h0;
        *(__half2*)(po + (row0+8)*HDIM + nj*8 + 2*cc) = h1;
    }
    if (cc == 0) {
        g_pm[u*QT + row0]     = m0;  g_pl[u*QT + row0]     = l0;
        g_pm[u*QT + row0 + 8] = m1;  g_pl[u*QT + row0 + 8] = l1;
    }
}

// ---------------------------------------------------------------------------
// Combine (2 rows/thread, MLP 8) + wo transpose in one launch.
// blocks [0,1024): combine; blocks [1024, 1024+4096): wo 32x32 transpose tiles.
// ---------------------------------------------------------------------------
__global__ void combine_wo(const float* __restrict__ wo, __half* __restrict__ wt_o)
{
    __shared__ float t[32][33];
    if (blockIdx.x < 1024) {
        int pair = blockIdx.x * 32 + (threadIdx.x >> 3);   // 2-row group
        int cs   = (threadIdx.x & 7) * 16;
        #pragma unroll
        for (int rr = 0; rr < 2; rr++) {
            int rlin = pair * 2 + rr;
            int qrow = rlin & 63;
            int qt   = (rlin >> 6) & (NQT-1);
            int h    = (rlin >> 11) & (NHEAD-1);
            int b    = (rlin >> 15) & 1;

            int u0 = ((0*BATCH + b)*NHEAD + h)*NQT + qt;
            int u1 = ((1*BATCH + b)*NHEAD + h)*NQT + qt;

            float m0 = g_pm[u0*QT + qrow], l0 = g_pl[u0*QT + qrow];
            float m1 = g_pm[u1*QT + qrow], l1 = g_pl[u1*QT + qrow];
            float M  = fmaxf(m0, m1);
            float w0 = __expf(m0 - M), w1 = __expf(m1 - M);
            float inv = 1.f / (w0*l0 + w1*l1);
            float f0 = w0 * inv, f1 = w1 * inv;

            const __half* p0 = g_po + (size_t)u0*(QT*HDIM) + qrow*HDIM + cs;
            const __half* p1 = g_po + (size_t)u1*(QT*HDIM) + qrow*HDIM + cs;
            __half* dst = g_att + ((size_t)(b*SEQ + qt*QT + qrow))*D_MODEL + h*HDIM + cs;

            #pragma unroll
            for (int half16 = 0; half16 < 2; half16++) {
                uint4 r0 = *(const uint4*)(p0 + half16*8);
                uint4 r1 = *(const uint4*)(p1 + half16*8);
                const __half2* a = (const __half2*)&r0;
                const __half2* c = (const __half2*)&r1;
                __half2 hh[4];
                #pragma unroll
                for (int j = 0; j < 4; j++) {
                    float2 fa = __half22float2(a[j]);
                    float2 fc = __half22float2(c[j]);
                    hh[j] = __floats2half2_rn(f0*fa.x + f1*fc.x, f0*fa.y + f1*fc.y);
                }
                *(uint4*)(dst + half16*8) = *(const uint4*)hh;
            }
        }
    } else {
        int tb = blockIdx.x - 1024;                 // 0..4095
        int bx = (tb & 63) * 32, by = (tb >> 6) * 32;
        int tx = threadIdx.x & 31, ty = threadIdx.x >> 5;  // 32 x 8
        int xcol = bx + tx;
        #pragma unroll
        for (int i = 0; i < 32; i += 8)
            t[ty + i][tx] = wo[(size_t)(by + ty + i) * D_MODEL + xcol];
        __syncthreads();
        xcol = by + tx;
        #pragma unroll
        for (int i = 0; i < 32; i += 8)
            wt_o[(size_t)(bx + ty + i) * D_MODEL + xcol] = __float2half(t[tx][ty + i]);
    }
}

// ---------------------------------------------------------------------------
// Launch
// ---------------------------------------------------------------------------
extern "C" void kernel_launch(void* const* d_in, const int* in_sizes, int n_in,
                              void* d_out, int out_size)
{
    (void)in_sizes; (void)n_in; (void)out_size;
    const float* x  = (const float*)d_in[0];
    const float* ck = (const float*)d_in[1];
    const float* cv = (const float*)d_in[2];
    const float* wq = (const float*)d_in[3];
    const float* bq = (const float*)d_in[4];
    const float* wk = (const float*)d_in[5];
    const float* bk = (const float*)d_in[6];
    const float* wv = (const float*)d_in[7];
    const float* bv = (const float*)d_in[8];
    const float* wo = (const float*)d_in[9];
    const float* bo = (const float*)d_in[10];
    float* out = (float*)d_out;

    __half *pxh, *pq, *pk, *pv, *pa, *pckh, *pcvh, *pw;
    cudaGetSymbolAddress((void**)&pxh,  g_xh);
    cudaGetSymbolAddress((void**)&pq,   g_q);
    cudaGetSymbolAddress((void**)&pk,   g_k);
    cudaGetSymbolAddress((void**)&pv,   g_v);
    cudaGetSymbolAddress((void**)&pa,   g_att);
    cudaGetSymbolAddress((void**)&pckh, g_ck);
    cudaGetSymbolAddress((void**)&pcvh, g_cv);
    cudaGetSymbolAddress((void**)&pw,   g_wt);

    __half* wt_o = pw + 3*(size_t)D_MODEL*D_MODEL;

    cudaFuncSetAttribute(gemm_qkv, cudaFuncAttributeMaxDynamicSharedMemorySize, GEMM_DSMEM);
    cudaFuncSetAttribute(gemm_o,   cudaFuncAttributeMaxDynamicSharedMemorySize, GEMM_DSMEM);
    cudaFuncSetAttribute(attn_h,   cudaFuncAttributeMaxDynamicSharedMemorySize, ATTN_SMEM_H);

    // Prep (critical path only: x convert, ck/cv convert, wq/wk/wv transpose)
    prep_all<<<dim3(MROWS*D_MODEL/8/256, 6), 256>>>(
        x, ck, cv, wq, wk, wv, pxh, pckh, pcvh, pw);

    // Fused QKV projection
    gemm_qkv<<<dim3(3*D_MODEL/GBN, MROWS/GBM), 256, GEMM_DSMEM>>>(
        pxh, pw, bq, bk, bv, pq, pk, pv);

    // Attention: split-KV partials
    dim3 ag(NQT*2, NHEAD, BATCH);
    attn_h<<<ag, 128, ATTN_SMEM_H>>>();

    // Combine (high-ILP) + wo transpose in one launch
    combine_wo<<<1024 + 4096, 256>>>(wo, wt_o);

    // Output projection (fp32 out)
    gemm_o<<<dim3(D_MODEL/GBN, MROWS/GBM), 256, GEMM_DSMEM>>>(pa, wt_o, bo, out);
}

// round 14
// speedup vs baseline: 1.5312x; 1.5312x over previous
#include <cuda_runtime.h>
#include <cuda_fp16.h>
#include <cstdint>
#include <cstddef>

// Problem constants
#define D_MODEL 2048
#define SEQ     2048
#define PAST    2048
#define NHEAD   16
#define HDIM    128
#define BATCH   2
#define MROWS   (BATCH*SEQ)     // 4096
#define KVTOT   (PAST+SEQ)      // 4096
#define NQT     (SEQ/64)        // 32 q-tiles per (b,h)

// Scratch (device globals — allocation-free per harness rules)
__device__ __half g_xh [MROWS*D_MODEL];               // fp16 x
__device__ __half g_q  [MROWS*D_MODEL];
__device__ __half g_k  [MROWS*D_MODEL];
__device__ __half g_v  [MROWS*D_MODEL];
__device__ __half g_att[MROWS*D_MODEL];
__device__ __half g_ck [BATCH*PAST*D_MODEL];          // fp16 cache_k (natural)
__device__ __half g_cv [BATCH*PAST*D_MODEL];          // fp16 cache_v (natural)
__device__ __half g_wt [4*(size_t)D_MODEL*D_MODEL];   // transposed fp16 weights (q,k,v,o)
// split-KV partials: [kvh][b][h][qt][64 rows][128 cols]
__device__ __half g_po [2*BATCH*NHEAD*NQT*64*128];    // 67 MB
__device__ float  g_pm [2*BATCH*NHEAD*NQT*64];
__device__ float  g_pl [2*BATCH*NHEAD*NQT*64];

// ---------------------------------------------------------------------------
// helpers
// ---------------------------------------------------------------------------
__device__ __forceinline__ uint32_t smem_u32(const void* p) {
    uint32_t a;
    asm("{ .reg .u64 t; cvta.to.shared.u64 t, %1; cvt.u32.u64 %0, t; }" : "=r"(a) : "l"(p));
    return a;
}
__device__ __forceinline__ void cp_async16(uint32_t sdst, const void* gsrc) {
    asm volatile("cp.async.cg.shared.global [%0], [%1], 16;" :: "r"(sdst), "l"(gsrc));
}
__device__ __forceinline__ void cp_commit() {
    asm volatile("cp.async.commit_group;");
}
template<int N>
__device__ __forceinline__ void cp_wait() {
    asm volatile("cp.async.wait_group %0;" :: "n"(N));
}
__device__ __forceinline__ void mma_h(float& c0, float& c1, float& c2, float& c3,
                                      uint32_t a0, uint32_t a1, uint32_t a2, uint32_t a3,
                                      uint32_t b0, uint32_t b1) {
    asm volatile("mma.sync.aligned.m16n8k16.row.col.f32.f16.f16.f32 "
                 "{%0,%1,%2,%3}, {%4,%5,%6,%7}, {%8,%9}, {%0,%1,%2,%3};"
                 : "+f"(c0), "+f"(c1), "+f"(c2), "+f"(c3)
                 : "r"(a0), "r"(a1), "r"(a2), "r"(a3), "r"(b0), "r"(b1));
}
__device__ __forceinline__ void ldsm_x4(uint32_t& r0, uint32_t& r1, uint32_t& r2, uint32_t& r3,
                                        uint32_t addr) {
    asm volatile("ldmatrix.sync.aligned.m8n8.x4.shared.b16 {%0,%1,%2,%3}, [%4];"
                 : "=r"(r0), "=r"(r1), "=r"(r2), "=r"(r3) : "r"(addr));
}
__device__ __forceinline__ void ldsm_x4_t(uint32_t& r0, uint32_t& r1, uint32_t& r2, uint32_t& r3,
                                          uint32_t addr) {
    asm volatile("ldmatrix.sync.aligned.m8n8.x4.trans.shared.b16 {%0,%1,%2,%3}, [%4];"
                 : "=r"(r0), "=r"(r1), "=r"(r2), "=r"(r3) : "r"(addr));
}

// ---------------------------------------------------------------------------
// fp16 GEMM core (CTA 128x256, BK=64, 8 warps/256thr, warp 64x64, 3-stage)
// ---------------------------------------------------------------------------
#define GBM 128
#define GBN 256
#define GBK 64
#define SWH 72
#define AS_H (GBM*SWH)
#define BS_H (GBN*SWH)
#define STG_H (AS_H+BS_H)
#define GSTG 3
#define GEMM_DSMEM (GSTG*STG_H*2)
#define NCHUNK (D_MODEL/GBK)

struct GemmCore {
    __device__ static void run(const __half* A, const __half* Bt,
                               const float* bias, void* Cout, int half_out,
                               int m0, int n0glob, int ncol0, __half* sh)
    {
        const uint32_t sbase = smem_u32(sh);
        const int tid  = threadIdx.x;
        const int wid  = tid >> 5;
        const int lane = tid & 31;
        const int r    = lane >> 2;
        const int cc   = lane & 3;
        const int wm = (wid >> 2) * 64;
        const int wn = (wid & 3) * 64;

        const int row8 = tid >> 3;
        const int seg  = tid & 7;
        const __half* Ag = A  + (size_t)(m0 + row8) * D_MODEL + seg * 8;
        const __half* Bg = Bt + (size_t)(n0glob + row8) * D_MODEL + seg * 8;

        float c[4][8][4];
        #pragma unroll
        for (int mi = 0; mi < 4; mi++)
            #pragma unroll
            for (int ni = 0; ni < 8; ni++)
                #pragma unroll
                for (int j = 0; j < 4; j++) c[mi][ni][j] = 0.f;

        auto load_chunk = [&](int chunk, int st) {
            uint32_t as = sbase + (st*STG_H) * 2;
            uint32_t bs = as + AS_H * 2;
            const __half* ag = Ag + chunk * GBK;
            const __half* bg = Bg + chunk * GBK;
            #pragma unroll
            for (int i = 0; i < 4; i++) {
                int row = row8 + i * 32;
                cp_async16(as + (uint32_t)(row*SWH + seg*8)*2, ag + (size_t)i*32*D_MODEL);
            }
            #pragma unroll
            for (int i = 0; i < 8; i++) {
                int row = row8 + i * 32;
                cp_async16(bs + (uint32_t)(row*SWH + seg*8)*2, bg + (size_t)i*32*D_MODEL);
            }
            cp_commit();
        };

        load_chunk(0, 0);
        load_chunk(1, 1);
        load_chunk(2, 2);

        for (int ch = 0; ch < NCHUNK; ch++) {
            int rem = NCHUNK - 1 - ch;
            if (rem >= 2)      cp_wait<2>();
            else if (rem == 1) cp_wait<1>();
            else               cp_wait<0>();
            __syncthreads();

            int st = ch % GSTG;
            const uint32_t* As32 = (const uint32_t*)(sh + st * STG_H);
            const uint32_t* Bs32 = As32 + AS_H/2;
            const uint32_t* pA = As32 + (wm + r) * (SWH/2) + cc;
            const uint32_t* pB = Bs32 + (wn + r) * (SWH/2) + cc;

            #pragma unroll
            for (int ks = 0; ks < 4; ks++) {
                uint32_t a[4][4];
                #pragma unroll
                for (int mi = 0; mi < 4; mi++) {
                    const uint32_t* p = pA + mi*16*(SWH/2) + ks*8;
                    a[mi][0] = p[0];
                    a[mi][1] = p[8*(SWH/2)];
                    a[mi][2] = p[4];
                    a[mi][3] = p[8*(SWH/2) + 4];
                }
                uint32_t b[8][2];
                #pragma unroll
                for (int ni = 0; ni < 8; ni++) {
                    const uint32_t* p = pB + ni*8*(SWH/2) + ks*8;
                    b[ni][0] = p[0];
                    b[ni][1] = p[4];
                }
                #pragma unroll
                for (int mi = 0; mi < 4; mi++)
                    #pragma unroll
                    for (int ni = 0; ni < 8; ni++)
                        mma_h(c[mi][ni][0], c[mi][ni][1], c[mi][ni][2], c[mi][ni][3],
                              a[mi][0], a[mi][1], a[mi][2], a[mi][3],
                              b[ni][0], b[ni][1]);
            }
            __syncthreads();
            if (ch + GSTG < NCHUNK) load_chunk(ch + GSTG, st);
        }

        #pragma unroll
        for (int mi = 0; mi < 4; mi++) {
            int row = m0 + wm + mi*16 + r;
            #pragma unroll
            for (int ni = 0; ni < 8; ni++) {
                int col = ncol0 + wn + ni*8 + cc*2;
                float2 bv = *(const float2*)(bias + col);
                float o00 = c[mi][ni][0] + bv.x, o01 = c[mi][ni][1] + bv.y;
                float o10 = c[mi][ni][2] + bv.x, o11 = c[mi][ni][3] + bv.y;
                if (half_out) {
                    __half* Ch = (__half*)Cout;
                    *(__half2*)(Ch + (size_t)row*D_MODEL + col)     = __floats2half2_rn(o00, o01);
                    *(__half2*)(Ch + (size_t)(row+8)*D_MODEL + col) = __floats2half2_rn(o10, o11);
                } else {
                    float* Cf = (float*)Cout;
                    *(float2*)(Cf + (size_t)row*D_MODEL + col)     = make_float2(o00, o01);
                    *(float2*)(Cf + (size_t)(row+8)*D_MODEL + col) = make_float2(o10, o11);
                }
            }
        }
    }
};

// fused QKV: Bt rows 0..6143 = wq^T | wk^T | wv^T
__global__ __launch_bounds__(256, 1)
void gemm_qkv(const __half* __restrict__ A, const __half* __restrict__ BtAll,
              const float* __restrict__ bq, const float* __restrict__ bk,
              const float* __restrict__ bv,
              __half* __restrict__ Cq, __half* __restrict__ Ck, __half* __restrict__ Cv)
{
    extern __shared__ __half sh[];
    int n0g = blockIdx.x * GBN;
    int mat = n0g >> 11;
    const float* bias = (mat == 0) ? bq : (mat == 1) ? bk : bv;
    __half* C = (mat == 0) ? Cq : (mat == 1) ? Ck : Cv;
    GemmCore::run(A, BtAll, bias, C, 1, blockIdx.y * GBM, n0g, n0g & 2047, sh);
}

__global__ __launch_bounds__(256, 1)
void gemm_o(const __half* __restrict__ A, const __half* __restrict__ Bt,
            const float* __restrict__ bias, float* __restrict__ C)
{
    extern __shared__ __half sh[];
    int n0 = blockIdx.x * GBN;
    GemmCore::run(A, Bt, bias, C, 0, blockIdx.y * GBM, n0, n0, sh);
}

// ---------------------------------------------------------------------------
// Fused prep: y=0..2 -> fp16 convert (x, cache_k, cache_v); y=3..6 -> weight
// transpose (wq,wk,wv,wo -> g_wt).
// ---------------------------------------------------------------------------
__global__ __launch_bounds__(256, 4)
void prep_all(const float* __restrict__ x, const float* __restrict__ ck,
              const float* __restrict__ cv,
              const float* __restrict__ wq, const float* __restrict__ wk,
              const float* __restrict__ wv, const float* __restrict__ wo,
              __half* __restrict__ dx, __half* __restrict__ dck,
              __half* __restrict__ dcv, __half* __restrict__ dw)
{
    __shared__ float t[32][33];
    int y = blockIdx.y;
    if (y < 3) {
        const float* src = (y == 0) ? x : (y == 1) ? ck : cv;
        __half* dst = (y == 0) ? dx : (y == 1) ? dck : dcv;
        int i = (blockIdx.x * blockDim.x + threadIdx.x) * 8;
        float4 f0 = *(const float4*)(src + i);
        float4 f1 = *(const float4*)(src + i + 4);
        __half2 h[4];
        h[0] = __floats2half2_rn(f0.x, f0.y);
        h[1] = __floats2half2_rn(f0.z, f0.w);
        h[2] = __floats2half2_rn(f1.x, f1.y);
        h[3] = __floats2half2_rn(f1.z, f1.w);
        *(uint4*)(dst + i) = *(const uint4*)h;
    } else {
        int z = y - 3;
        const float* src = (z == 0) ? wq : (z == 1) ? wk : (z == 2) ? wv : wo;
        __half* dst = dw + (size_t)z * D_MODEL * D_MODEL;
        int bx = (blockIdx.x & 63) * 32, by = (blockIdx.x >> 6) * 32;
        int tx = threadIdx.x & 31, ty = threadIdx.x >> 5;  // 32 x 8
        int xcol = bx + tx;
        #pragma unroll
        for (int i = 0; i < 32; i += 8)
            t[ty + i][tx] = src[(size_t)(by + ty + i) * D_MODEL + xcol];
        __syncthreads();
        xcol = by + tx;
        #pragma unroll
        for (int i = 0; i < 32; i += 8)
            dst[(size_t)(bx + ty + i) * D_MODEL + xcol] = __float2half(t[tx][ty + i]);
    }
}

// ---------------------------------------------------------------------------
// fp16 flash attention, split-KV (128 thr, occ 2, gmem partials).
// ---------------------------------------------------------------------------
#define QT 64
#define KT 64
#define NTH (KVTOT/KT/2)       // 32 tiles per half
#define SQH 136                // row stride (halfs)
#define OFF_Q      0
#define OFF_K(st)  (8704 + (st)*8704)
#define OFF_V(st)  (26112 + (st)*8704)
#define ATTN_SMEM_H ((26112 + 2*8704)*2)   // 87040 bytes

__global__ __launch_bounds__(128, 2)
void attn_h(void)
{
    extern __shared__ __half sm[];
    const uint32_t sbase = smem_u32(sm);
    const int tid  = threadIdx.x;
    const int wid  = tid >> 5;
    const int lane = tid & 31;
    const int r    = lane >> 2;
    const int cc   = lane & 3;
    const int qt   = blockIdx.x >> 1;
    const int kvh  = blockIdx.x & 1;
    const int h  = blockIdx.y;
    const int b  = blockIdx.z;
    const int q0 = qt * QT;
    const int t0 = kvh * NTH;

    // Q load (group 0)
    {
        const __half* qg = g_q + ((size_t)(b*SEQ + q0))*D_MODEL + h*HDIM;
        #pragma unroll
        for (int i = 0; i < 8; i++) {
            int s = tid + i*128;
            int row = s >> 4, seg = s & 15;
            cp_async16(sbase + (uint32_t)(OFF_Q + row*SQH + seg*8)*2,
                       qg + (size_t)row*D_MODEL + seg*8);
        }
        cp_commit();
    }

    auto load_tile = [&](int t, int st) {
        int kv0 = t * KT;
        const __half *kb, *vb;
        if (kv0 < PAST) {
            size_t off = ((size_t)(b*PAST + kv0))*D_MODEL + h*HDIM;
            kb = g_ck + off; vb = g_cv + off;
        } else {
            size_t off = ((size_t)(b*SEQ + (kv0-PAST)))*D_MODEL + h*HDIM;
            kb = g_k + off; vb = g_v + off;
        }
        #pragma unroll
        for (int i = 0; i < 8; i++) {
            int s = tid + i*128;
            int row = s >> 4, seg = s & 15;
            cp_async16(sbase + (uint32_t)(OFF_K(st) + row*SQH + seg*8)*2,
                       kb + (size_t)row*D_MODEL + seg*8);
            cp_async16(sbase + (uint32_t)(OFF_V(st) + row*SQH + seg*8)*2,
                       vb + (size_t)row*D_MODEL + seg*8);
        }
        cp_commit();
    };

    load_tile(t0, 0);
    load_tile(t0 + 1, 1);
    cp_wait<1>();
    __syncthreads();

    // ---- hoist Q A-fragments (unscaled fp16; scale applied in fp32 post-MMA)
    uint32_t qa[8][4];
    {
        int g  = lane >> 3, kr = lane & 7;
        int qrow = wid*16 + (g & 1)*8 + kr;
        int cbase = (g >> 1)*8;
        #pragma unroll
        for (int kb = 0; kb < 8; kb++) {
            uint32_t addr = sbase + (uint32_t)(OFF_Q + qrow*SQH + kb*16 + cbase)*2;
            ldsm_x4(qa[kb][0], qa[kb][1], qa[kb][2], qa[kb][3], addr);
        }
    }

    float o[16][4];
    #pragma unroll
    for (int nj = 0; nj < 16; nj++)
        #pragma unroll
        for (int j = 0; j < 4; j++) o[nj][j] = 0.f;
    float m0 = -1e30f, m1 = -1e30f, l0 = 0.f, l1 = 0.f;

    const float sc = 0.08838834764831845f;   // 1/sqrt(128)

    const int kg = lane >> 3, kkr = lane & 7;
    const int k_row_off = (kg >> 1)*8 + kkr;
    const int k_col_off = (kg & 1)*8;
    const int v_row_off = lane & 15;
    const int v_col_off = (lane >> 4)*8;

    for (int lt = 0; lt < NTH; lt++) {
        const uint32_t kbase = sbase + (uint32_t)OFF_K(lt & 1)*2;
        const uint32_t vbase = sbase + (uint32_t)OFF_V(lt & 1)*2;

        // ---- S = Q @ K^T (m16 n64 k128)
        float s[8][4];
        #pragma unroll
        for (int ni = 0; ni < 8; ni++)
            #pragma unroll
            for (int j = 0; j < 4; j++) s[ni][j] = 0.f;

        #pragma unroll
        for (int np = 0; np < 4; np++) {
            #pragma unroll
            for (int kb = 0; kb < 8; kb++) {
                uint32_t b0, b1, b2, b3;
                uint32_t addr = kbase + (uint32_t)((np*16 + k_row_off)*SQH + kb*16 + k_col_off)*2;
                ldsm_x4(b0, b1, b2, b3, addr);
                mma_h(s[2*np][0], s[2*np][1], s[2*np][2], s[2*np][3],
                      qa[kb][0], qa[kb][1], qa[kb][2], qa[kb][3], b0, b1);
                mma_h(s[2*np+1][0], s[2*np+1][1], s[2*np+1][2], s[2*np+1][3],
                      qa[kb][0], qa[kb][1], qa[kb][2], qa[kb][3], b2, b3);
            }
        }

        // ---- online softmax (rows r and r+8)
        float mx0 = -1e30f, mx1 = -1e30f;
        #pragma unroll
        for (int ni = 0; ni < 8; ni++) {
            s[ni][0] *= sc; s[ni][1] *= sc; s[ni][2] *= sc; s[ni][3] *= sc;
            mx0 = fmaxf(mx0, fmaxf(s[ni][0], s[ni][1]));
            mx1 = fmaxf(mx1, fmaxf(s[ni][2], s[ni][3]));
        }
        mx0 = fmaxf(mx0, __shfl_xor_sync(0xffffffffu, mx0, 1));
        mx0 = fmaxf(mx0, __shfl_xor_sync(0xffffffffu, mx0, 2));
        mx1 = fmaxf(mx1, __shfl_xor_sync(0xffffffffu, mx1, 1));
        mx1 = fmaxf(mx1, __shfl_xor_sync(0xffffffffu, mx1, 2));

        float nm0 = fmaxf(m0, mx0), nm1 = fmaxf(m1, mx1);
        float al0 = __expf(m0 - nm0), al1 = __expf(m1 - nm1);
        float sum0 = 0.f, sum1 = 0.f;
        #pragma unroll
        for (int ni = 0; ni < 8; ni++) {
            s[ni][0] = __expf(s[ni][0] - nm0);
            s[ni][1] = __expf(s[ni][1] - nm0);
            s[ni][2] = __expf(s[ni][2] - nm1);
            s[ni][3] = __expf(s[ni][3] - nm1);
            sum0 += s[ni][0] + s[ni][1];
            sum1 += s[ni][2] + s[ni][3];
        }
        sum0 += __shfl_xor_sync(0xffffffffu, sum0, 1);
        sum0 += __shfl_xor_sync(0xffffffffu, sum0, 2);
        sum1 += __shfl_xor_sync(0xffffffffu, sum1, 1);
        sum1 += __shfl_xor_sync(0xffffffffu, sum1, 2);
        l0 = l0*al0 + sum0;  m0 = nm0;
        l1 = l1*al1 + sum1;  m1 = nm1;

        #pragma unroll
        for (int nj = 0; nj < 16; nj++) {
            o[nj][0] *= al0; o[nj][1] *= al0;
            o[nj][2] *= al1; o[nj][3] *= al1;
        }

        // ---- P: C-fragment -> A-fragment register repack
        uint32_t pa[4][4];
        #pragma unroll
        for (int ks = 0; ks < 4; ks++) {
            __half2 h00 = __floats2half2_rn(s[2*ks][0],   s[2*ks][1]);
            __half2 h01 = __floats2half2_rn(s[2*ks][2],   s[2*ks][3]);
            __half2 h10 = __floats2half2_rn(s[2*ks+1][0], s[2*ks+1][1]);
            __half2 h11 = __floats2half2_rn(s[2*ks+1][2], s[2*ks+1][3]);
            pa[ks][0] = *(uint32_t*)&h00;
            pa[ks][1] = *(uint32_t*)&h01;
            pa[ks][2] = *(uint32_t*)&h10;
            pa[ks][3] = *(uint32_t*)&h11;
        }

        // ---- O += P @ V (m16 n128 k64); B frags via ldmatrix.trans on natural V
        #pragma unroll
        for (int np = 0; np < 8; np++) {
            #pragma unroll
            for (int ks = 0; ks < 4; ks++) {
                uint32_t v0, v1, v2, v3;
                uint32_t addr = vbase + (uint32_t)((ks*16 + v_row_off)*SQH + np*16 + v_col_off)*2;
                ldsm_x4_t(v0, v1, v2, v3, addr);
                mma_h(o[2*np][0], o[2*np][1], o[2*np][2], o[2*np][3],
                      pa[ks][0], pa[ks][1], pa[ks][2], pa[ks][3], v0, v1);
                mma_h(o[2*np+1][0], o[2*np+1][1], o[2*np+1][2], o[2*np+1][3],
                      pa[ks][0], pa[ks][1], pa[ks][2], pa[ks][3], v2, v3);
            }
        }

        __syncthreads();
        if (lt + 1 < NTH) {
            if (lt + 2 < NTH) { load_tile(t0 + lt + 2, lt & 1); cp_wait<1>(); }
            else              cp_wait<0>();
            __syncthreads();
        }
    }

    // ---- store unnormalized fp16 partials + (m,l)
    const int u = ((kvh*BATCH + b)*NHEAD + h)*NQT + qt;
    __half* po = g_po + (size_t)u * (QT*HDIM);
    const int row0 = wid*16 + r;
    #pragma unroll
    for (int nj = 0; nj < 16; nj++) {
        __half2 h0 = __floats2half2_rn(o[nj][0], o[nj][1]);
        __half2 h1 = __floats2half2_rn(o[nj][2], o[nj][3]);
        *(__half2*)(po + row0*HDIM     + nj*8 + 2*cc) = h0;
        *(__half2*)(po + (row0+8)*HDIM + nj*8 + 2*cc) = h1;
    }
    if (cc == 0) {
        g_pm[u*QT + row0]     = m0;  g_pl[u*QT + row0]     = l0;
        g_pm[u*QT + row0 + 8] = m1;  g_pl[u*QT + row0 + 8] = l1;
    }
}

// ---------------------------------------------------------------------------
// Combine the two KV halves -> fp16 g_att
// ---------------------------------------------------------------------------
__global__ void attn_combine(void)
{
    int rlin = blockIdx.x * 16 + (threadIdx.x >> 4);
    int cs   = (threadIdx.x & 15) * 8;
    int qrow = rlin & 63;
    int qt   = (rlin >> 6) & (NQT-1);
    int h    = (rlin >> 11) & (NHEAD-1);
    int b    = (rlin >> 15) & 1;

    int u0 = ((0*BATCH + b)*NHEAD + h)*NQT + qt;
    int u1 = ((1*BATCH + b)*NHEAD + h)*NQT + qt;

    float m0 = g_pm[u0*QT + qrow], l0 = g_pl[u0*QT + qrow];
    float m1 = g_pm[u1*QT + qrow], l1 = g_pl[u1*QT + qrow];
    float M  = fmaxf(m0, m1);
    float w0 = __expf(m0 - M), w1 = __expf(m1 - M);
    float inv = 1.f / (w0*l0 + w1*l1);
    float f0 = w0 * inv, f1 = w1 * inv;

    const __half* p0 = g_po + (size_t)u0*(QT*HDIM) + qrow*HDIM + cs;
    const __half* p1 = g_po + (size_t)u1*(QT*HDIM) + qrow*HDIM + cs;
    uint4 r0 = *(const uint4*)p0;
    uint4 r1 = *(const uint4*)p1;
    const __half2* a = (const __half2*)&r0;
    const __half2* c = (const __half2*)&r1;

    __half2 hh[4];
    #pragma unroll
    for (int j = 0; j < 4; j++) {
        float2 fa = __half22float2(a[j]);
        float2 fc = __half22float2(c[j]);
        hh[j] = __floats2half2_rn(f0*fa.x + f1*fc.x, f0*fa.y + f1*fc.y);
    }

    __half* dst = g_att + ((size_t)(b*SEQ + qt*QT + qrow))*D_MODEL + h*HDIM + cs;
    *(uint4*)dst = *(const uint4*)hh;
}

// ---------------------------------------------------------------------------
// Launch
// ---------------------------------------------------------------------------
extern "C" void kernel_launch(void* const* d_in, const int* in_sizes, int n_in,
                              void* d_out, int out_size)
{
    (void)in_sizes; (void)n_in; (void)out_size;
    const float* x  = (const float*)d_in[0];
    const float* ck = (const float*)d_in[1];
    const float* cv = (const float*)d_in[2];
    const float* wq = (const float*)d_in[3];
    const float* bq = (const float*)d_in[4];
    const float* wk = (const float*)d_in[5];
    const float* bk = (const float*)d_in[6];
    const float* wv = (const float*)d_in[7];
    const float* bv = (const float*)d_in[8];
    const float* wo = (const float*)d_in[9];
    const float* bo = (const float*)d_in[10];
    float* out = (float*)d_out;

    __half *pxh, *pq, *pk, *pv, *pa, *pckh, *pcvh, *pw;
    cudaGetSymbolAddress((void**)&pxh,  g_xh);
    cudaGetSymbolAddress((void**)&pq,   g_q);
    cudaGetSymbolAddress((void**)&pk,   g_k);
    cudaGetSymbolAddress((void**)&pv,   g_v);
    cudaGetSymbolAddress((void**)&pa,   g_att);
    cudaGetSymbolAddress((void**)&pckh, g_ck);
    cudaGetSymbolAddress((void**)&pcvh, g_cv);
    cudaGetSymbolAddress((void**)&pw,   g_wt);

    __half* wt_o = pw + 3*(size_t)D_MODEL*D_MODEL;

    cudaFuncSetAttribute(gemm_qkv, cudaFuncAttributeMaxDynamicSharedMemorySize, GEMM_DSMEM);
    cudaFuncSetAttribute(gemm_o,   cudaFuncAttributeMaxDynamicSharedMemorySize, GEMM_DSMEM);
    cudaFuncSetAttribute(attn_h,   cudaFuncAttributeMaxDynamicSharedMemorySize, ATTN_SMEM_H);

    // Fused prep (converts + all four weight transposes) in one launch
    prep_all<<<dim3(MROWS*D_MODEL/8/256, 7), 256>>>(
        x, ck, cv, wq, wk, wv, wo, pxh, pckh, pcvh, pw);

    // Fused QKV projection
    gemm_qkv<<<dim3(3*D_MODEL/GBN, MROWS/GBM), 256, GEMM_DSMEM>>>(
        pxh, pw, bq, bk, bv, pq, pk, pv);

    // Attention: split-KV + combine
    dim3 ag(NQT*2, NHEAD, BATCH);
    attn_h<<<ag, 128, ATTN_SMEM_H>>>();
    attn_combine<<<(BATCH*NHEAD*NQT*QT)/16, 256>>>();

    // Output projection (fp32 out)
    gemm_o<<<dim3(D_MODEL/GBN, MROWS/GBM), 256, GEMM_DSMEM>>>(pa, wt_o, bo, out);
}

// round 15
// speedup vs baseline: 1.5475x; 1.0106x over previous
#include <cuda_runtime.h>
#include <cuda_fp16.h>
#include <cstdint>
#include <cstddef>

// Problem constants
#define D_MODEL 2048
#define SEQ     2048
#define PAST    2048
#define NHEAD   16
#define HDIM    128
#define BATCH   2
#define MROWS   (BATCH*SEQ)     // 4096
#define KVTOT   (PAST+SEQ)      // 4096
#define NQT     (SEQ/64)        // 32 q-tiles per (b,h)

// Scratch (device globals — allocation-free per harness rules)
__device__ __half g_xh [MROWS*D_MODEL];               // fp16 x
__device__ __half g_q  [MROWS*D_MODEL];
__device__ __half g_k  [MROWS*D_MODEL];
__device__ __half g_v  [MROWS*D_MODEL];
__device__ __half g_att[MROWS*D_MODEL];
__device__ __half g_ck [BATCH*PAST*D_MODEL];          // fp16 cache_k (natural)
__device__ __half g_cv [BATCH*PAST*D_MODEL];          // fp16 cache_v (natural)
__device__ __half g_wt [4*(size_t)D_MODEL*D_MODEL];   // transposed fp16 weights (q,k,v,o)
// split-KV partials: [kvh][b][h][qt][64 rows][128 cols]; m,l in log2 domain
__device__ __half g_po [2*BATCH*NHEAD*NQT*64*128];    // 67 MB
__device__ float  g_pm [2*BATCH*NHEAD*NQT*64];
__device__ float  g_pl [2*BATCH*NHEAD*NQT*64];

// ---------------------------------------------------------------------------
// helpers
// ---------------------------------------------------------------------------
__device__ __forceinline__ uint32_t smem_u32(const void* p) {
    uint32_t a;
    asm("{ .reg .u64 t; cvta.to.shared.u64 t, %1; cvt.u32.u64 %0, t; }" : "=r"(a) : "l"(p));
    return a;
}
__device__ __forceinline__ void cp_async16(uint32_t sdst, const void* gsrc) {
    asm volatile("cp.async.cg.shared.global [%0], [%1], 16;" :: "r"(sdst), "l"(gsrc));
}
__device__ __forceinline__ void cp_commit() {
    asm volatile("cp.async.commit_group;");
}
template<int N>
__device__ __forceinline__ void cp_wait() {
    asm volatile("cp.async.wait_group %0;" :: "n"(N));
}
__device__ __forceinline__ void mma_h(float& c0, float& c1, float& c2, float& c3,
                                      uint32_t a0, uint32_t a1, uint32_t a2, uint32_t a3,
                                      uint32_t b0, uint32_t b1) {
    asm volatile("mma.sync.aligned.m16n8k16.row.col.f32.f16.f16.f32 "
                 "{%0,%1,%2,%3}, {%4,%5,%6,%7}, {%8,%9}, {%0,%1,%2,%3};"
                 : "+f"(c0), "+f"(c1), "+f"(c2), "+f"(c3)
                 : "r"(a0), "r"(a1), "r"(a2), "r"(a3), "r"(b0), "r"(b1));
}
__device__ __forceinline__ void ldsm_x4(uint32_t& r0, uint32_t& r1, uint32_t& r2, uint32_t& r3,
                                        uint32_t addr) {
    asm volatile("ldmatrix.sync.aligned.m8n8.x4.shared.b16 {%0,%1,%2,%3}, [%4];"
                 : "=r"(r0), "=r"(r1), "=r"(r2), "=r"(r3) : "r"(addr));
}
__device__ __forceinline__ void ldsm_x4_t(uint32_t& r0, uint32_t& r1, uint32_t& r2, uint32_t& r3,
                                          uint32_t addr) {
    asm volatile("ldmatrix.sync.aligned.m8n8.x4.trans.shared.b16 {%0,%1,%2,%3}, [%4];"
                 : "=r"(r0), "=r"(r1), "=r"(r2), "=r"(r3) : "r"(addr));
}
__device__ __forceinline__ float ex2(float x) {
    float y;
    asm("ex2.approx.f32 %0, %1;" : "=f"(y) : "f"(x));
    return y;
}

// ---------------------------------------------------------------------------
// fp16 GEMM core (CTA 128x256, BK=64, 8 warps/256thr, warp 64x64, 3-stage)
// ---------------------------------------------------------------------------
#define GBM 128
#define GBN 256
#define GBK 64
#define SWH 72
#define AS_H (GBM*SWH)
#define BS_H (GBN*SWH)
#define STG_H (AS_H+BS_H)
#define GSTG 3
#define GEMM_DSMEM (GSTG*STG_H*2)
#define NCHUNK (D_MODEL/GBK)

struct GemmCore {
    __device__ static void run(const __half* A, const __half* Bt,
                               const float* bias, void* Cout, int half_out,
                               int m0, int n0glob, int ncol0, __half* sh)
    {
        const uint32_t sbase = smem_u32(sh);
        const int tid  = threadIdx.x;
        const int wid  = tid >> 5;
        const int lane = tid & 31;
        const int r    = lane >> 2;
        const int cc   = lane & 3;
        const int wm = (wid >> 2) * 64;
        const int wn = (wid & 3) * 64;

        const int row8 = tid >> 3;
        const int seg  = tid & 7;
        const __half* Ag = A  + (size_t)(m0 + row8) * D_MODEL + seg * 8;
        const __half* Bg = Bt + (size_t)(n0glob + row8) * D_MODEL + seg * 8;

        float c[4][8][4];
        #pragma unroll
        for (int mi = 0; mi < 4; mi++)
            #pragma unroll
            for (int ni = 0; ni < 8; ni++)
                #pragma unroll
                for (int j = 0; j < 4; j++) c[mi][ni][j] = 0.f;

        auto load_chunk = [&](int chunk, int st) {
            uint32_t as = sbase + (st*STG_H) * 2;
            uint32_t bs = as + AS_H * 2;
            const __half* ag = Ag + chunk * GBK;
            const __half* bg = Bg + chunk * GBK;
            #pragma unroll
            for (int i = 0; i < 4; i++) {
                int row = row8 + i * 32;
                cp_async16(as + (uint32_t)(row*SWH + seg*8)*2, ag + (size_t)i*32*D_MODEL);
            }
            #pragma unroll
            for (int i = 0; i < 8; i++) {
                int row = row8 + i * 32;
                cp_async16(bs + (uint32_t)(row*SWH + seg*8)*2, bg + (size_t)i*32*D_MODEL);
            }
            cp_commit();
        };

        load_chunk(0, 0);
        load_chunk(1, 1);
        load_chunk(2, 2);

        for (int ch = 0; ch < NCHUNK; ch++) {
            int rem = NCHUNK - 1 - ch;
            if (rem >= 2)      cp_wait<2>();
            else if (rem == 1) cp_wait<1>();
            else               cp_wait<0>();
            __syncthreads();

            int st = ch % GSTG;
            const uint32_t* As32 = (const uint32_t*)(sh + st * STG_H);
            const uint32_t* Bs32 = As32 + AS_H/2;
            const uint32_t* pA = As32 + (wm + r) * (SWH/2) + cc;
            const uint32_t* pB = Bs32 + (wn + r) * (SWH/2) + cc;

            #pragma unroll
            for (int ks = 0; ks < 4; ks++) {
                uint32_t a[4][4];
                #pragma unroll
                for (int mi = 0; mi < 4; mi++) {
                    const uint32_t* p = pA + mi*16*(SWH/2) + ks*8;
                    a[mi][0] = p[0];
                    a[mi][1] = p[8*(SWH/2)];
                    a[mi][2] = p[4];
                    a[mi][3] = p[8*(SWH/2) + 4];
                }
                uint32_t b[8][2];
                #pragma unroll
                for (int ni = 0; ni < 8; ni++) {
                    const uint32_t* p = pB + ni*8*(SWH/2) + ks*8;
                    b[ni][0] = p[0];
                    b[ni][1] = p[4];
                }
                #pragma unroll
                for (int mi = 0; mi < 4; mi++)
                    #pragma unroll
                    for (int ni = 0; ni < 8; ni++)
                        mma_h(c[mi][ni][0], c[mi][ni][1], c[mi][ni][2], c[mi][ni][3],
                              a[mi][0], a[mi][1], a[mi][2], a[mi][3],
                              b[ni][0], b[ni][1]);
            }
            __syncthreads();
            if (ch + GSTG < NCHUNK) load_chunk(ch + GSTG, st);
        }

        #pragma unroll
        for (int mi = 0; mi < 4; mi++) {
            int row = m0 + wm + mi*16 + r;
            #pragma unroll
            for (int ni = 0; ni < 8; ni++) {
                int col = ncol0 + wn + ni*8 + cc*2;
                float2 bv = *(const float2*)(bias + col);
                float o00 = c[mi][ni][0] + bv.x, o01 = c[mi][ni][1] + bv.y;
                float o10 = c[mi][ni][2] + bv.x, o11 = c[mi][ni][3] + bv.y;
                if (half_out) {
                    __half* Ch = (__half*)Cout;
                    *(__half2*)(Ch + (size_t)row*D_MODEL + col)     = __floats2half2_rn(o00, o01);
                    *(__half2*)(Ch + (size_t)(row+8)*D_MODEL + col) = __floats2half2_rn(o10, o11);
                } else {
                    float* Cf = (float*)Cout;
                    *(float2*)(Cf + (size_t)row*D_MODEL + col)     = make_float2(o00, o01);
                    *(float2*)(Cf + (size_t)(row+8)*D_MODEL + col) = make_float2(o10, o11);
                }
            }
        }
    }
};

// fused QKV: Bt rows 0..6143 = wq^T | wk^T | wv^T
__global__ __launch_bounds__(256, 1)
void gemm_qkv(const __half* __restrict__ A, const __half* __restrict__ BtAll,
              const float* __restrict__ bq, const float* __restrict__ bk,
              const float* __restrict__ bv,
              __half* __restrict__ Cq, __half* __restrict__ Ck, __half* __restrict__ Cv)
{
    extern __shared__ __half sh[];
    int n0g = blockIdx.x * GBN;
    int mat = n0g >> 11;
    const float* bias = (mat == 0) ? bq : (mat == 1) ? bk : bv;
    __half* C = (mat == 0) ? Cq : (mat == 1) ? Ck : Cv;
    GemmCore::run(A, BtAll, bias, C, 1, blockIdx.y * GBM, n0g, n0g & 2047, sh);
}

__global__ __launch_bounds__(256, 1)
void gemm_o(const __half* __restrict__ A, const __half* __restrict__ Bt,
            const float* __restrict__ bias, float* __restrict__ C)
{
    extern __shared__ __half sh[];
    int n0 = blockIdx.x * GBN;
    GemmCore::run(A, Bt, bias, C, 0, blockIdx.y * GBM, n0, n0, sh);
}

// ---------------------------------------------------------------------------
// Fused prep: y=0..2 -> fp16 convert (x, cache_k, cache_v); y=3..6 -> weight
// transpose (wq,wk,wv,wo -> g_wt).
// ---------------------------------------------------------------------------
__global__ __launch_bounds__(256, 4)
void prep_all(const float* __restrict__ x, const float* __restrict__ ck,
              const float* __restrict__ cv,
              const float* __restrict__ wq, const float* __restrict__ wk,
              const float* __restrict__ wv, const float* __restrict__ wo,
              __half* __restrict__ dx, __half* __restrict__ dck,
              __half* __restrict__ dcv, __half* __restrict__ dw)
{
    __shared__ float t[32][33];
    int y = blockIdx.y;
    if (y < 3) {
        const float* src = (y == 0) ? x : (y == 1) ? ck : cv;
        __half* dst = (y == 0) ? dx : (y == 1) ? dck : dcv;
        int i = (blockIdx.x * blockDim.x + threadIdx.x) * 8;
        float4 f0 = *(const float4*)(src + i);
        float4 f1 = *(const float4*)(src + i + 4);
        __half2 h[4];
        h[0] = __floats2half2_rn(f0.x, f0.y);
        h[1] = __floats2half2_rn(f0.z, f0.w);
        h[2] = __floats2half2_rn(f1.x, f1.y);
        h[3] = __floats2half2_rn(f1.z, f1.w);
        *(uint4*)(dst + i) = *(const uint4*)h;
    } else {
        int z = y - 3;
        const float* src = (z == 0) ? wq : (z == 1) ? wk : (z == 2) ? wv : wo;
        __half* dst = dw + (size_t)z * D_MODEL * D_MODEL;
        int bx = (blockIdx.x & 63) * 32, by = (blockIdx.x >> 6) * 32;
        int tx = threadIdx.x & 31, ty = threadIdx.x >> 5;  // 32 x 8
        int xcol = bx + tx;
        #pragma unroll
        for (int i = 0; i < 32; i += 8)
            t[ty + i][tx] = src[(size_t)(by + ty + i) * D_MODEL + xcol];
        __syncthreads();
        xcol = by + tx;
        #pragma unroll
        for (int i = 0; i < 32; i += 8)
            dst[(size_t)(bx + ty + i) * D_MODEL + xcol] = __float2half(t[tx][ty + i]);
    }
}

// ---------------------------------------------------------------------------
// fp16 flash attention, split-KV (128 thr, occ 2, gmem partials).
// Softmax in exp2 domain (fp32): S *= sc*log2(e), exp2f; m/l log2-domain.
// ---------------------------------------------------------------------------
#define QT 64
#define KT 64
#define NTH (KVTOT/KT/2)       // 32 tiles per half
#define SQH 136                // row stride (halfs)
#define OFF_Q      0
#define OFF_K(st)  (8704 + (st)*8704)
#define OFF_V(st)  (26112 + (st)*8704)
#define ATTN_SMEM_H ((26112 + 2*8704)*2)   // 87040 bytes

__global__ __launch_bounds__(128, 2)
void attn_h(void)
{
    extern __shared__ __half sm[];
    const uint32_t sbase = smem_u32(sm);
    const int tid  = threadIdx.x;
    const int wid  = tid >> 5;
    const int lane = tid & 31;
    const int r    = lane >> 2;
    const int cc   = lane & 3;
    const int qt   = blockIdx.x >> 1;
    const int kvh  = blockIdx.x & 1;
    const int h  = blockIdx.y;
    const int b  = blockIdx.z;
    const int q0 = qt * QT;
    const int t0 = kvh * NTH;

    // Q load (group 0)
    {
        const __half* qg = g_q + ((size_t)(b*SEQ + q0))*D_MODEL + h*HDIM;
        #pragma unroll
        for (int i = 0; i < 8; i++) {
            int s = tid + i*128;
            int row = s >> 4, seg = s & 15;
            cp_async16(sbase + (uint32_t)(OFF_Q + row*SQH + seg*8)*2,
                       qg + (size_t)row*D_MODEL + seg*8);
        }
        cp_commit();
    }

    auto load_tile = [&](int t, int st) {
        int kv0 = t * KT;
        const __half *kb, *vb;
        if (kv0 < PAST) {
            size_t off = ((size_t)(b*PAST + kv0))*D_MODEL + h*HDIM;
            kb = g_ck + off; vb = g_cv + off;
        } else {
            size_t off = ((size_t)(b*SEQ + (kv0-PAST)))*D_MODEL + h*HDIM;
            kb = g_k + off; vb = g_v + off;
        }
        #pragma unroll
        for (int i = 0; i < 8; i++) {
            int s = tid + i*128;
            int row = s >> 4, seg = s & 15;
            cp_async16(sbase + (uint32_t)(OFF_K(st) + row*SQH + seg*8)*2,
                       kb + (size_t)row*D_MODEL + seg*8);
            cp_async16(sbase + (uint32_t)(OFF_V(st) + row*SQH + seg*8)*2,
                       vb + (size_t)row*D_MODEL + seg*8);
        }
        cp_commit();
    };

    load_tile(t0, 0);
    load_tile(t0 + 1, 1);
    cp_wait<1>();
    __syncthreads();

    // ---- hoist Q A-fragments (unscaled fp16; scale applied in fp32 post-MMA)
    uint32_t qa[8][4];
    {
        int g  = lane >> 3, kr = lane & 7;
        int qrow = wid*16 + (g & 1)*8 + kr;
        int cbase = (g >> 1)*8;
        #pragma unroll
        for (int kb = 0; kb < 8; kb++) {
            uint32_t addr = sbase + (uint32_t)(OFF_Q + qrow*SQH + kb*16 + cbase)*2;
            ldsm_x4(qa[kb][0], qa[kb][1], qa[kb][2], qa[kb][3], addr);
        }
    }

    float o[16][4];
    #pragma unroll
    for (int nj = 0; nj < 16; nj++)
        #pragma unroll
        for (int j = 0; j < 4; j++) o[nj][j] = 0.f;
    float m0 = -1e30f, m1 = -1e30f, l0 = 0.f, l1 = 0.f;

    const float sc2 = 0.12751879523f;   // (1/sqrt(128)) * log2(e)

    const int kg = lane >> 3, kkr = lane & 7;
    const int k_row_off = (kg >> 1)*8 + kkr;
    const int k_col_off = (kg & 1)*8;
    const int v_row_off = lane & 15;
    const int v_col_off = (lane >> 4)*8;

    for (int lt = 0; lt < NTH; lt++) {
        const uint32_t kbase = sbase + (uint32_t)OFF_K(lt & 1)*2;
        const uint32_t vbase = sbase + (uint32_t)OFF_V(lt & 1)*2;

        // ---- S = Q @ K^T (m16 n64 k128)
        float s[8][4];
        #pragma unroll
        for (int ni = 0; ni < 8; ni++)
            #pragma unroll
            for (int j = 0; j < 4; j++) s[ni][j] = 0.f;

        #pragma unroll
        for (int np = 0; np < 4; np++) {
            #pragma unroll
            for (int kb = 0; kb < 8; kb++) {
                uint32_t b0, b1, b2, b3;
                uint32_t addr = kbase + (uint32_t)((np*16 + k_row_off)*SQH + kb*16 + k_col_off)*2;
                ldsm_x4(b0, b1, b2, b3, addr);
                mma_h(s[2*np][0], s[2*np][1], s[2*np][2], s[2*np][3],
                      qa[kb][0], qa[kb][1], qa[kb][2], qa[kb][3], b0, b1);
                mma_h(s[2*np+1][0], s[2*np+1][1], s[2*np+1][2], s[2*np+1][3],
                      qa[kb][0], qa[kb][1], qa[kb][2], qa[kb][3], b2, b3);
            }
        }

        // ---- online softmax in exp2 domain (rows r and r+8)
        float mx0 = -1e30f, mx1 = -1e30f;
        #pragma unroll
        for (int ni = 0; ni < 8; ni++) {
            s[ni][0] *= sc2; s[ni][1] *= sc2; s[ni][2] *= sc2; s[ni][3] *= sc2;
            mx0 = fmaxf(mx0, fmaxf(s[ni][0], s[ni][1]));
            mx1 = fmaxf(mx1, fmaxf(s[ni][2], s[ni][3]));
        }
        mx0 = fmaxf(mx0, __shfl_xor_sync(0xffffffffu, mx0, 1));
        mx0 = fmaxf(mx0, __shfl_xor_sync(0xffffffffu, mx0, 2));
        mx1 = fmaxf(mx1, __shfl_xor_sync(0xffffffffu, mx1, 1));
        mx1 = fmaxf(mx1, __shfl_xor_sync(0xffffffffu, mx1, 2));

        float nm0 = fmaxf(m0, mx0), nm1 = fmaxf(m1, mx1);
        float al0 = ex2(m0 - nm0), al1 = ex2(m1 - nm1);
        float sum0 = 0.f, sum1 = 0.f;
        #pragma unroll
        for (int ni = 0; ni < 8; ni++) {
            s[ni][0] = ex2(s[ni][0] - nm0);
            s[ni][1] = ex2(s[ni][1] - nm0);
            s[ni][2] = ex2(s[ni][2] - nm1);
            s[ni][3] = ex2(s[ni][3] - nm1);
            sum0 += s[ni][0] + s[ni][1];
            sum1 += s[ni][2] + s[ni][3];
        }
        sum0 += __shfl_xor_sync(0xffffffffu, sum0, 1);
        sum0 += __shfl_xor_sync(0xffffffffu, sum0, 2);
        sum1 += __shfl_xor_sync(0xffffffffu, sum1, 1);
        sum1 += __shfl_xor_sync(0xffffffffu, sum1, 2);
        l0 = l0*al0 + sum0;  m0 = nm0;
        l1 = l1*al1 + sum1;  m1 = nm1;

        #pragma unroll
        for (int nj = 0; nj < 16; nj++) {
            o[nj][0] *= al0; o[nj][1] *= al0;
            o[nj][2] *= al1; o[nj][3] *= al1;
        }

        // ---- P: C-fragment -> A-fragment register repack
        uint32_t pa[4][4];
        #pragma unroll
        for (int ks = 0; ks < 4; ks++) {
            __half2 h00 = __floats2half2_rn(s[2*ks][0],   s[2*ks][1]);
            __half2 h01 = __floats2half2_rn(s[2*ks][2],   s[2*ks][3]);
            __half2 h10 = __floats2half2_rn(s[2*ks+1][0], s[2*ks+1][1]);
            __half2 h11 = __floats2half2_rn(s[2*ks+1][2], s[2*ks+1][3]);
            pa[ks][0] = *(uint32_t*)&h00;
            pa[ks][1] = *(uint32_t*)&h01;
            pa[ks][2] = *(uint32_t*)&h10;
            pa[ks][3] = *(uint32_t*)&h11;
        }

        // ---- O += P @ V (m16 n128 k64); B frags via ldmatrix.trans on natural V
        #pragma unroll
        for (int np = 0; np < 8; np++) {
            #pragma unroll
            for (int ks = 0; ks < 4; ks++) {
                uint32_t v0, v1, v2, v3;
                uint32_t addr = vbase + (uint32_t)((ks*16 + v_row_off)*SQH + np*16 + v_col_off)*2;
                ldsm_x4_t(v0, v1, v2, v3, addr);
                mma_h(o[2*np][0], o[2*np][1], o[2*np][2], o[2*np][3],
                      pa[ks][0], pa[ks][1], pa[ks][2], pa[ks][3], v0, v1);
                mma_h(o[2*np+1][0], o[2*np+1][1], o[2*np+1][2], o[2*np+1][3],
                      pa[ks][0], pa[ks][1], pa[ks][2], pa[ks][3], v2, v3);
            }
        }

        __syncthreads();
        if (lt + 1 < NTH) {
            if (lt + 2 < NTH) { load_tile(t0 + lt + 2, lt & 1); cp_wait<1>(); }
            else              cp_wait<0>();
            __syncthreads();
        }
    }

    // ---- store unnormalized fp16 partials + (m,l) [log2 domain]
    const int u = ((kvh*BATCH + b)*NHEAD + h)*NQT + qt;
    __half* po = g_po + (size_t)u * (QT*HDIM);
    const int row0 = wid*16 + r;
    #pragma unroll
    for (int nj = 0; nj < 16; nj++) {
        __half2 h0 = __floats2half2_rn(o[nj][0], o[nj][1]);
        __half2 h1 = __floats2half2_rn(o[nj][2], o[nj][3]);
        *(__half2*)(po + row0*HDIM     + nj*8 + 2*cc) = h0;
        *(__half2*)(po + (row0+8)*HDIM + nj*8 + 2*cc) = h1;
    }
    if (cc == 0) {
        g_pm[u*QT + row0]     = m0;  g_pl[u*QT + row0]     = l0;
        g_pm[u*QT + row0 + 8] = m1;  g_pl[u*QT + row0 + 8] = l1;
    }
}

// ---------------------------------------------------------------------------
// Combine the two KV halves -> fp16 g_att  (m in log2 domain -> exp2)
// ---------------------------------------------------------------------------
__global__ void attn_combine(void)
{
    int rlin = blockIdx.x * 16 + (threadIdx.x >> 4);
    int cs   = (threadIdx.x & 15) * 8;
    int qrow = rlin & 63;
    int qt   = (rlin >> 6) & (NQT-1);
    int h    = (rlin >> 11) & (NHEAD-1);
    int b    = (rlin >> 15) & 1;

    int u0 = ((0*BATCH + b)*NHEAD + h)*NQT + qt;
    int u1 = ((1*BATCH + b)*NHEAD + h)*NQT + qt;

    float m0 = g_pm[u0*QT + qrow], l0 = g_pl[u0*QT + qrow];
    float m1 = g_pm[u1*QT + qrow], l1 = g_pl[u1*QT + qrow];
    float M  = fmaxf(m0, m1);
    float w0 = exp2f(m0 - M), w1 = exp2f(m1 - M);
    float inv = 1.f / (w0*l0 + w1*l1);
    float f0 = w0 * inv, f1 = w1 * inv;

    const __half* p0 = g_po + (size_t)u0*(QT*HDIM) + qrow*HDIM + cs;
    const __half* p1 = g_po + (size_t)u1*(QT*HDIM) + qrow*HDIM + cs;
    uint4 r0 = *(const uint4*)p0;
    uint4 r1 = *(const uint4*)p1;
    const __half2* a = (const __half2*)&r0;
    const __half2* c = (const __half2*)&r1;

    __half2 hh[4];
    #pragma unroll
    for (int j = 0; j < 4; j++) {
        float2 fa = __half22float2(a[j]);
        float2 fc = __half22float2(c[j]);
        hh[j] = __floats2half2_rn(f0*fa.x + f1*fc.x, f0*fa.y + f1*fc.y);
    }

    __half* dst = g_att + ((size_t)(b*SEQ + qt*QT + qrow))*D_MODEL + h*HDIM + cs;
    *(uint4*)dst = *(const uint4*)hh;
}

// ---------------------------------------------------------------------------
// Launch
// ---------------------------------------------------------------------------
extern "C" void kernel_launch(void* const* d_in, const int* in_sizes, int n_in,
                              void* d_out, int out_size)
{
    (void)in_sizes; (void)n_in; (void)out_size;
    const float* x  = (const float*)d_in[0];
    const float* ck = (const float*)d_in[1];
    const float* cv = (const float*)d_in[2];
    const float* wq = (const float*)d_in[3];
    const float* bq = (const float*)d_in[4];
    const float* wk = (const float*)d_in[5];
    const float* bk = (const float*)d_in[6];
    const float* wv = (const float*)d_in[7];
    const float* bv = (const float*)d_in[8];
    const float* wo = (const float*)d_in[9];
    const float* bo = (const float*)d_in[10];
    float* out = (float*)d_out;

    __half *pxh, *pq, *pk, *pv, *pa, *pckh, *pcvh, *pw;
    cudaGetSymbolAddress((void**)&pxh,  g_xh);
    cudaGetSymbolAddress((void**)&pq,   g_q);
    cudaGetSymbolAddress((void**)&pk,   g_k);
    cudaGetSymbolAddress((void**)&pv,   g_v);
    cudaGetSymbolAddress((void**)&pa,   g_att);
    cudaGetSymbolAddress((void**)&pckh, g_ck);
    cudaGetSymbolAddress((void**)&pcvh, g_cv);
    cudaGetSymbolAddress((void**)&pw,   g_wt);

    __half* wt_o = pw + 3*(size_t)D_MODEL*D_MODEL;

    cudaFuncSetAttribute(gemm_qkv, cudaFuncAttributeMaxDynamicSharedMemorySize, GEMM_DSMEM);
    cudaFuncSetAttribute(gemm_o,   cudaFuncAttributeMaxDynamicSharedMemorySize, GEMM_DSMEM);
    cudaFuncSetAttribute(attn_h,   cudaFuncAttributeMaxDynamicSharedMemorySize, ATTN_SMEM_H);

    // Fused prep (converts + all four weight transposes) in one launch
    prep_all<<<dim3(MROWS*D_MODEL/8/256, 7), 256>>>(
        x, ck, cv, wq, wk, wv, wo, pxh, pckh, pcvh, pw);

    // Fused QKV projection
    gemm_qkv<<<dim3(3*D_MODEL/GBN, MROWS/GBM), 256, GEMM_DSMEM>>>(
        pxh, pw, bq, bk, bv, pq, pk, pv);

    // Attention: split-KV + combine
    dim3 ag(NQT*2, NHEAD, BATCH);
    attn_h<<<ag, 128, ATTN_SMEM_H>>>();
    attn_combine<<<(BATCH*NHEAD*NQT*QT)/16, 256>>>();

    // Output projection (fp32 out)
    gemm_o<<<dim3(D_MODEL/GBN, MROWS/GBM), 256, GEMM_DSMEM>>>(pa, wt_o, bo, out);
}

// round 16
// speedup vs baseline: 1.5643x; 1.0109x over previous
#include <cuda_runtime.h>
#include <cuda_fp16.h>
#include <cstdint>
#include <cstddef>

// Problem constants
#define D_MODEL 2048
#define SEQ     2048
#define PAST    2048
#define NHEAD   16
#define HDIM    128
#define BATCH   2
#define MROWS   (BATCH*SEQ)     // 4096
#define KVTOT   (PAST+SEQ)      // 4096
#define NQT     (SEQ/64)        // 32 q-tiles per (b,h)

// Scratch (device globals — allocation-free per harness rules)
__device__ __half g_xh [MROWS*D_MODEL];               // fp16 x
__device__ __half g_q  [MROWS*D_MODEL];               // Q pre-scaled by sc*log2(e)
__device__ __half g_k  [MROWS*D_MODEL];
__device__ __half g_v  [MROWS*D_MODEL];
__device__ __half g_att[MROWS*D_MODEL];
__device__ __half g_ck [BATCH*PAST*D_MODEL];          // fp16 cache_k (natural)
__device__ __half g_cv [BATCH*PAST*D_MODEL];          // fp16 cache_v (natural)
__device__ __half g_wt [4*(size_t)D_MODEL*D_MODEL];   // transposed fp16 weights (q,k,v,o)
// split-KV partials: [kvh][b][h][qt][64 rows][128 cols]; m,l in log2 domain
__device__ __half g_po [2*BATCH*NHEAD*NQT*64*128];    // 67 MB
__device__ float  g_pm [2*BATCH*NHEAD*NQT*64];
__device__ float  g_pl [2*BATCH*NHEAD*NQT*64];

// ---------------------------------------------------------------------------
// helpers
// ---------------------------------------------------------------------------
__device__ __forceinline__ uint32_t smem_u32(const void* p) {
    uint32_t a;
    asm("{ .reg .u64 t; cvta.to.shared.u64 t, %1; cvt.u32.u64 %0, t; }" : "=r"(a) : "l"(p));
    return a;
}
__device__ __forceinline__ void cp_async16(uint32_t sdst, const void* gsrc) {
    asm volatile("cp.async.cg.shared.global [%0], [%1], 16;" :: "r"(sdst), "l"(gsrc));
}
__device__ __forceinline__ void cp_commit() {
    asm volatile("cp.async.commit_group;");
}
template<int N>
__device__ __forceinline__ void cp_wait() {
    asm volatile("cp.async.wait_group %0;" :: "n"(N));
}
__device__ __forceinline__ void mma_h(float& c0, float& c1, float& c2, float& c3,
                                      uint32_t a0, uint32_t a1, uint32_t a2, uint32_t a3,
                                      uint32_t b0, uint32_t b1) {
    asm volatile("mma.sync.aligned.m16n8k16.row.col.f32.f16.f16.f32 "
                 "{%0,%1,%2,%3}, {%4,%5,%6,%7}, {%8,%9}, {%0,%1,%2,%3};"
                 : "+f"(c0), "+f"(c1), "+f"(c2), "+f"(c3)
                 : "r"(a0), "r"(a1), "r"(a2), "r"(a3), "r"(b0), "r"(b1));
}
__device__ __forceinline__ void ldsm_x4(uint32_t& r0, uint32_t& r1, uint32_t& r2, uint32_t& r3,
                                        uint32_t addr) {
    asm volatile("ldmatrix.sync.aligned.m8n8.x4.shared.b16 {%0,%1,%2,%3}, [%4];"
                 : "=r"(r0), "=r"(r1), "=r"(r2), "=r"(r3) : "r"(addr));
}
__device__ __forceinline__ void ldsm_x4_t(uint32_t& r0, uint32_t& r1, uint32_t& r2, uint32_t& r3,
                                          uint32_t addr) {
    asm volatile("ldmatrix.sync.aligned.m8n8.x4.trans.shared.b16 {%0,%1,%2,%3}, [%4];"
                 : "=r"(r0), "=r"(r1), "=r"(r2), "=r"(r3) : "r"(addr));
}
__device__ __forceinline__ float ex2(float x) {
    float y;
    asm("ex2.approx.f32 %0, %1;" : "=f"(y) : "f"(x));
    return y;
}

// ---------------------------------------------------------------------------
// fp16 GEMM core (CTA 128x256, BK=64, 8 warps/256thr, warp 64x64, 3-stage).
// out_scale multiplies (acc + bias) in fp32 before the single fp16 rounding.
// ---------------------------------------------------------------------------
#define GBM 128
#define GBN 256
#define GBK 64
#define SWH 72
#define AS_H (GBM*SWH)
#define BS_H (GBN*SWH)
#define STG_H (AS_H+BS_H)
#define GSTG 3
#define GEMM_DSMEM (GSTG*STG_H*2)
#define NCHUNK (D_MODEL/GBK)

struct GemmCore {
    __device__ static void run(const __half* A, const __half* Bt,
                               const float* bias, void* Cout, int half_out,
                               float out_scale,
                               int m0, int n0glob, int ncol0, __half* sh)
    {
        const uint32_t sbase = smem_u32(sh);
        const int tid  = threadIdx.x;
        const int wid  = tid >> 5;
        const int lane = tid & 31;
        const int r    = lane >> 2;
        const int cc   = lane & 3;
        const int wm = (wid >> 2) * 64;
        const int wn = (wid & 3) * 64;

        const int row8 = tid >> 3;
        const int seg  = tid & 7;
        const __half* Ag = A  + (size_t)(m0 + row8) * D_MODEL + seg * 8;
        const __half* Bg = Bt + (size_t)(n0glob + row8) * D_MODEL + seg * 8;

        float c[4][8][4];
        #pragma unroll
        for (int mi = 0; mi < 4; mi++)
            #pragma unroll
            for (int ni = 0; ni < 8; ni++)
                #pragma unroll
                for (int j = 0; j < 4; j++) c[mi][ni][j] = 0.f;

        auto load_chunk = [&](int chunk, int st) {
            uint32_t as = sbase + (st*STG_H) * 2;
            uint32_t bs = as + AS_H * 2;
            const __half* ag = Ag + chunk * GBK;
            const __half* bg = Bg + chunk * GBK;
            #pragma unroll
            for (int i = 0; i < 4; i++) {
                int row = row8 + i * 32;
                cp_async16(as + (uint32_t)(row*SWH + seg*8)*2, ag + (size_t)i*32*D_MODEL);
            }
            #pragma unroll
            for (int i = 0; i < 8; i++) {
                int row = row8 + i * 32;
                cp_async16(bs + (uint32_t)(row*SWH + seg*8)*2, bg + (size_t)i*32*D_MODEL);
            }
            cp_commit();
        };

        load_chunk(0, 0);
        load_chunk(1, 1);
        load_chunk(2, 2);

        for (int ch = 0; ch < NCHUNK; ch++) {
            int rem = NCHUNK - 1 - ch;
            if (rem >= 2)      cp_wait<2>();
            else if (rem == 1) cp_wait<1>();
            else               cp_wait<0>();
            __syncthreads();

            int st = ch % GSTG;
            const uint32_t* As32 = (const uint32_t*)(sh + st * STG_H);
            const uint32_t* Bs32 = As32 + AS_H/2;
            const uint32_t* pA = As32 + (wm + r) * (SWH/2) + cc;
            const uint32_t* pB = Bs32 + (wn + r) * (SWH/2) + cc;

            #pragma unroll
            for (int ks = 0; ks < 4; ks++) {
                uint32_t a[4][4];
                #pragma unroll
                for (int mi = 0; mi < 4; mi++) {
                    const uint32_t* p = pA + mi*16*(SWH/2) + ks*8;
                    a[mi][0] = p[0];
                    a[mi][1] = p[8*(SWH/2)];
                    a[mi][2] = p[4];
                    a[mi][3] = p[8*(SWH/2) + 4];
                }
                uint32_t b[8][2];
                #pragma unroll
                for (int ni = 0; ni < 8; ni++) {
                    const uint32_t* p = pB + ni*8*(SWH/2) + ks*8;
                    b[ni][0] = p[0];
                    b[ni][1] = p[4];
                }
                #pragma unroll
                for (int mi = 0; mi < 4; mi++)
                    #pragma unroll
                    for (int ni = 0; ni < 8; ni++)
                        mma_h(c[mi][ni][0], c[mi][ni][1], c[mi][ni][2], c[mi][ni][3],
                              a[mi][0], a[mi][1], a[mi][2], a[mi][3],
                              b[ni][0], b[ni][1]);
            }
            __syncthreads();
            if (ch + GSTG < NCHUNK) load_chunk(ch + GSTG, st);
        }

        #pragma unroll
        for (int mi = 0; mi < 4; mi++) {
            int row = m0 + wm + mi*16 + r;
            #pragma unroll
            for (int ni = 0; ni < 8; ni++) {
                int col = ncol0 + wn + ni*8 + cc*2;
                float2 bv = *(const float2*)(bias + col);
                float o00 = (c[mi][ni][0] + bv.x) * out_scale;
                float o01 = (c[mi][ni][1] + bv.y) * out_scale;
                float o10 = (c[mi][ni][2] + bv.x) * out_scale;
                float o11 = (c[mi][ni][3] + bv.y) * out_scale;
                if (half_out) {
                    __half* Ch = (__half*)Cout;
                    *(__half2*)(Ch + (size_t)row*D_MODEL + col)     = __floats2half2_rn(o00, o01);
                    *(__half2*)(Ch + (size_t)(row+8)*D_MODEL + col) = __floats2half2_rn(o10, o11);
                } else {
                    float* Cf = (float*)Cout;
                    *(float2*)(Cf + (size_t)row*D_MODEL + col)     = make_float2(o00, o01);
                    *(float2*)(Cf + (size_t)(row+8)*D_MODEL + col) = make_float2(o10, o11);
                }
            }
        }
    }
};

// (1/sqrt(128)) * log2(e): folded into the Q projection epilogue (fp32).
#define SC2F 0.12751879523f

// fused QKV: Bt rows 0..6143 = wq^T | wk^T | wv^T. Q output pre-scaled by SC2F.
__global__ __launch_bounds__(256, 1)
void gemm_qkv(const __half* __restrict__ A, const __half* __restrict__ BtAll,
              const float* __restrict__ bq, const float* __restrict__ bk,
              const float* __restrict__ bv,
              __half* __restrict__ Cq, __half* __restrict__ Ck, __half* __restrict__ Cv)
{
    extern __shared__ __half sh[];
    int n0g = blockIdx.x * GBN;
    int mat = n0g >> 11;
    const float* bias = (mat == 0) ? bq : (mat == 1) ? bk : bv;
    __half* C = (mat == 0) ? Cq : (mat == 1) ? Ck : Cv;
    float scale = (mat == 0) ? SC2F : 1.0f;
    GemmCore::run(A, BtAll, bias, C, 1, scale, blockIdx.y * GBM, n0g, n0g & 2047, sh);
}

__global__ __launch_bounds__(256, 1)
void gemm_o(const __half* __restrict__ A, const __half* __restrict__ Bt,
            const float* __restrict__ bias, float* __restrict__ C)
{
    extern __shared__ __half sh[];
    int n0 = blockIdx.x * GBN;
    GemmCore::run(A, Bt, bias, C, 0, 1.0f, blockIdx.y * GBM, n0, n0, sh);
}

// ---------------------------------------------------------------------------
// Fused prep: y=0..2 -> fp16 convert (x, cache_k, cache_v); y=3..6 -> weight
// transpose (wq,wk,wv,wo -> g_wt).
// ---------------------------------------------------------------------------
__global__ __launch_bounds__(256, 4)
void prep_all(const float* __restrict__ x, const float* __restrict__ ck,
              const float* __restrict__ cv,
              const float* __restrict__ wq, const float* __restrict__ wk,
              const float* __restrict__ wv, const float* __restrict__ wo,
              __half* __restrict__ dx, __half* __restrict__ dck,
              __half* __restrict__ dcv, __half* __restrict__ dw)
{
    __shared__ float t[32][33];
    int y = blockIdx.y;
    if (y < 3) {
        const float* src = (y == 0) ? x : (y == 1) ? ck : cv;
        __half* dst = (y == 0) ? dx : (y == 1) ? dck : dcv;
        int i = (blockIdx.x * blockDim.x + threadIdx.x) * 8;
        float4 f0 = *(const float4*)(src + i);
        float4 f1 = *(const float4*)(src + i + 4);
        __half2 h[4];
        h[0] = __floats2half2_rn(f0.x, f0.y);
        h[1] = __floats2half2_rn(f0.z, f0.w);
        h[2] = __floats2half2_rn(f1.x, f1.y);
        h[3] = __floats2half2_rn(f1.z, f1.w);
        *(uint4*)(dst + i) = *(const uint4*)h;
    } else {
        int z = y - 3;
        const float* src = (z == 0) ? wq : (z == 1) ? wk : (z == 2) ? wv : wo;
        __half* dst = dw + (size_t)z * D_MODEL * D_MODEL;
        int bx = (blockIdx.x & 63) * 32, by = (blockIdx.x >> 6) * 32;
        int tx = threadIdx.x & 31, ty = threadIdx.x >> 5;  // 32 x 8
        int xcol = bx + tx;
        #pragma unroll
        for (int i = 0; i < 32; i += 8)
            t[ty + i][tx] = src[(size_t)(by + ty + i) * D_MODEL + xcol];
        __syncthreads();
        xcol = by + tx;
        #pragma unroll
        for (int i = 0; i < 32; i += 8)
            dst[(size_t)(bx + ty + i) * D_MODEL + xcol] = __float2half(t[tx][ty + i]);
    }
}

// ---------------------------------------------------------------------------
// fp16 flash attention, split-KV (128 thr, occ 2, gmem partials).
// Q pre-scaled by sc*log2(e) in fp32 at projection time -> S is already in
// log2-softmax units; softmax is bare max/ex2/sum (no per-element scaling).
// ---------------------------------------------------------------------------
#define QT 64
#define KT 64
#define NTH (KVTOT/KT/2)       // 32 tiles per half
#define SQH 136                // row stride (halfs)
#define OFF_Q      0
#define OFF_K(st)  (8704 + (st)*8704)
#define OFF_V(st)  (26112 + (st)*8704)
#define ATTN_SMEM_H ((26112 + 2*8704)*2)   // 87040 bytes

__global__ __launch_bounds__(128, 2)
void attn_h(void)
{
    extern __shared__ __half sm[];
    const uint32_t sbase = smem_u32(sm);
    const int tid  = threadIdx.x;
    const int wid  = tid >> 5;
    const int lane = tid & 31;
    const int r    = lane >> 2;
    const int cc   = lane & 3;
    const int qt   = blockIdx.x >> 1;
    const int kvh  = blockIdx.x & 1;
    const int h  = blockIdx.y;
    const int b  = blockIdx.z;
    const int q0 = qt * QT;
    const int t0 = kvh * NTH;

    // Q load (group 0)
    {
        const __half* qg = g_q + ((size_t)(b*SEQ + q0))*D_MODEL + h*HDIM;
        #pragma unroll
        for (int i = 0; i < 8; i++) {
            int s = tid + i*128;
            int row = s >> 4, seg = s & 15;
            cp_async16(sbase + (uint32_t)(OFF_Q + row*SQH + seg*8)*2,
                       qg + (size_t)row*D_MODEL + seg*8);
        }
        cp_commit();
    }

    auto load_tile = [&](int t, int st) {
        int kv0 = t * KT;
        const __half *kb, *vb;
        if (kv0 < PAST) {
            size_t off = ((size_t)(b*PAST + kv0))*D_MODEL + h*HDIM;
            kb = g_ck + off; vb = g_cv + off;
        } else {
            size_t off = ((size_t)(b*SEQ + (kv0-PAST)))*D_MODEL + h*HDIM;
            kb = g_k + off; vb = g_v + off;
        }
        #pragma unroll
        for (int i = 0; i < 8; i++) {
            int s = tid + i*128;
            int row = s >> 4, seg = s & 15;
            cp_async16(sbase + (uint32_t)(OFF_K(st) + row*SQH + seg*8)*2,
                       kb + (size_t)row*D_MODEL + seg*8);
            cp_async16(sbase + (uint32_t)(OFF_V(st) + row*SQH + seg*8)*2,
                       vb + (size_t)row*D_MODEL + seg*8);
        }
        cp_commit();
    };

    load_tile(t0, 0);
    load_tile(t0 + 1, 1);
    cp_wait<1>();
    __syncthreads();

    // ---- hoist Q A-fragments (already scaled: S in log2 units post-MMA)
    uint32_t qa[8][4];
    {
        int g  = lane >> 3, kr = lane & 7;
        int qrow = wid*16 + (g & 1)*8 + kr;
        int cbase = (g >> 1)*8;
        #pragma unroll
        for (int kb = 0; kb < 8; kb++) {
            uint32_t addr = sbase + (uint32_t)(OFF_Q + qrow*SQH + kb*16 + cbase)*2;
            ldsm_x4(qa[kb][0], qa[kb][1], qa[kb][2], qa[kb][3], addr);
        }
    }

    float o[16][4];
    #pragma unroll
    for (int nj = 0; nj < 16; nj++)
        #pragma unroll
        for (int j = 0; j < 4; j++) o[nj][j] = 0.f;
    float m0 = -1e30f, m1 = -1e30f, l0 = 0.f, l1 = 0.f;

    const int kg = lane >> 3, kkr = lane & 7;
    const int k_row_off = (kg >> 1)*8 + kkr;
    const int k_col_off = (kg & 1)*8;
    const int v_row_off = lane & 15;
    const int v_col_off = (lane >> 4)*8;

    for (int lt = 0; lt < NTH; lt++) {
        const uint32_t kbase = sbase + (uint32_t)OFF_K(lt & 1)*2;
        const uint32_t vbase = sbase + (uint32_t)OFF_V(lt & 1)*2;

        // ---- S = Qs @ K^T (m16 n64 k128), S already in log2 units
        float s[8][4];
        #pragma unroll
        for (int ni = 0; ni < 8; ni++)
            #pragma unroll
            for (int j = 0; j < 4; j++) s[ni][j] = 0.f;

        #pragma unroll
        for (int np = 0; np < 4; np++) {
            #pragma unroll
            for (int kb = 0; kb < 8; kb++) {
                uint32_t b0, b1, b2, b3;
                uint32_t addr = kbase + (uint32_t)((np*16 + k_row_off)*SQH + kb*16 + k_col_off)*2;
                ldsm_x4(b0, b1, b2, b3, addr);
                mma_h(s[2*np][0], s[2*np][1], s[2*np][2], s[2*np][3],
                      qa[kb][0], qa[kb][1], qa[kb][2], qa[kb][3], b0, b1);
                mma_h(s[2*np+1][0], s[2*np+1][1], s[2*np+1][2], s[2*np+1][3],
                      qa[kb][0], qa[kb][1], qa[kb][2], qa[kb][3], b2, b3);
            }
        }

        // ---- online softmax in exp2 domain (rows r and r+8)
        float mx0 = -1e30f, mx1 = -1e30f;
        #pragma unroll
        for (int ni = 0; ni < 8; ni++) {
            mx0 = fmaxf(mx0, fmaxf(s[ni][0], s[ni][1]));
            mx1 = fmaxf(mx1, fmaxf(s[ni][2], s[ni][3]));
        }
        mx0 = fmaxf(mx0, __shfl_xor_sync(0xffffffffu, mx0, 1));
        mx0 = fmaxf(mx0, __shfl_xor_sync(0xffffffffu, mx0, 2));
        mx1 = fmaxf(mx1, __shfl_xor_sync(0xffffffffu, mx1, 1));
        mx1 = fmaxf(mx1, __shfl_xor_sync(0xffffffffu, mx1, 2));

        float nm0 = fmaxf(m0, mx0), nm1 = fmaxf(m1, mx1);
        float al0 = ex2(m0 - nm0), al1 = ex2(m1 - nm1);
        float sum0 = 0.f, sum1 = 0.f;
        #pragma unroll
        for (int ni = 0; ni < 8; ni++) {
            s[ni][0] = ex2(s[ni][0] - nm0);
            s[ni][1] = ex2(s[ni][1] - nm0);
            s[ni][2] = ex2(s[ni][2] - nm1);
            s[ni][3] = ex2(s[ni][3] - nm1);
            sum0 += s[ni][0] + s[ni][1];
            sum1 += s[ni][2] + s[ni][3];
        }
        sum0 += __shfl_xor_sync(0xffffffffu, sum0, 1);
        sum0 += __shfl_xor_sync(0xffffffffu, sum0, 2);
        sum1 += __shfl_xor_sync(0xffffffffu, sum1, 1);
        sum1 += __shfl_xor_sync(0xffffffffu, sum1, 2);
        l0 = l0*al0 + sum0;  m0 = nm0;
        l1 = l1*al1 + sum1;  m1 = nm1;

        #pragma unroll
        for (int nj = 0; nj < 16; nj++) {
            o[nj][0] *= al0; o[nj][1] *= al0;
            o[nj][2] *= al1; o[nj][3] *= al1;
        }

        // ---- P: C-fragment -> A-fragment register repack
        uint32_t pa[4][4];
        #pragma unroll
        for (int ks = 0; ks < 4; ks++) {
            __half2 h00 = __floats2half2_rn(s[2*ks][0],   s[2*ks][1]);
            __half2 h01 = __floats2half2_rn(s[2*ks][2],   s[2*ks][3]);
            __half2 h10 = __floats2half2_rn(s[2*ks+1][0], s[2*ks+1][1]);
            __half2 h11 = __floats2half2_rn(s[2*ks+1][2], s[2*ks+1][3]);
            pa[ks][0] = *(uint32_t*)&h00;
            pa[ks][1] = *(uint32_t*)&h01;
            pa[ks][2] = *(uint32_t*)&h10;
            pa[ks][3] = *(uint32_t*)&h11;
        }

        // ---- O += P @ V (m16 n128 k64); B frags via ldmatrix.trans on natural V
        #pragma unroll
        for (int np = 0; np < 8; np++) {
            #pragma unroll
            for (int ks = 0; ks < 4; ks++) {
                uint32_t v0, v1, v2, v3;
                uint32_t addr = vbase + (uint32_t)((ks*16 + v_row_off)*SQH + np*16 + v_col_off)*2;
                ldsm_x4_t(v0, v1, v2, v3, addr);
                mma_h(o[2*np][0], o[2*np][1], o[2*np][2], o[2*np][3],
                      pa[ks][0], pa[ks][1], pa[ks][2], pa[ks][3], v0, v1);
                mma_h(o[2*np+1][0], o[2*np+1][1], o[2*np+1][2], o[2*np+1][3],
                      pa[ks][0], pa[ks][1], pa[ks][2], pa[ks][3], v2, v3);
            }
        }

        __syncthreads();
        if (lt + 1 < NTH) {
            if (lt + 2 < NTH) { load_tile(t0 + lt + 2, lt & 1); cp_wait<1>(); }
            else              cp_wait<0>();
            __syncthreads();
        }
    }

    // ---- store unnormalized fp16 partials + (m,l) [log2 domain]
    const int u = ((kvh*BATCH + b)*NHEAD + h)*NQT + qt;
    __half* po = g_po + (size_t)u * (QT*HDIM);
    const int row0 = wid*16 + r;
    #pragma unroll
    for (int nj = 0; nj < 16; nj++) {
        __half2 h0 = __floats2half2_rn(o[nj][0], o[nj][1]);
        __half2 h1 = __floats2half2_rn(o[nj][2], o[nj][3]);
        *(__half2*)(po + row0*HDIM     + nj*8 + 2*cc) = h0;
        *(__half2*)(po + (row0+8)*HDIM + nj*8 + 2*cc) = h1;
    }
    if (cc == 0) {
        g_pm[u*QT + row0]     = m0;  g_pl[u*QT + row0]     = l0;
        g_pm[u*QT + row0 + 8] = m1;  g_pl[u*QT + row0 + 8] = l1;
    }
}

// ---------------------------------------------------------------------------
// Combine the two KV halves -> fp16 g_att  (m in log2 domain -> exp2)
// ---------------------------------------------------------------------------
__global__ void attn_combine(void)
{
    int rlin = blockIdx.x * 16 + (threadIdx.x >> 4);
    int cs   = (threadIdx.x & 15) * 8;
    int qrow = rlin & 63;
    int qt   = (rlin >> 6) & (NQT-1);
    int h    = (rlin >> 11) & (NHEAD-1);
    int b    = (rlin >> 15) & 1;

    int u0 = ((0*BATCH + b)*NHEAD + h)*NQT + qt;
    int u1 = ((1*BATCH + b)*NHEAD + h)*NQT + qt;

    float m0 = g_pm[u0*QT + qrow], l0 = g_pl[u0*QT + qrow];
    float m1 = g_pm[u1*QT + qrow], l1 = g_pl[u1*QT + qrow];
    float M  = fmaxf(m0, m1);
    float w0 = exp2f(m0 - M), w1 = exp2f(m1 - M);
    float inv = 1.f / (w0*l0 + w1*l1);
    float f0 = w0 * inv, f1 = w1 * inv;

    const __half* p0 = g_po + (size_t)u0*(QT*HDIM) + qrow*HDIM + cs;
    const __half* p1 = g_po + (size_t)u1*(QT*HDIM) + qrow*HDIM + cs;
    uint4 r0 = *(const uint4*)p0;
    uint4 r1 = *(const uint4*)p1;
    const __half2* a = (const __half2*)&r0;
    const __half2* c = (const __half2*)&r1;

    __half2 hh[4];
    #pragma unroll
    for (int j = 0; j < 4; j++) {
        float2 fa = __half22float2(a[j]);
        float2 fc = __half22float2(c[j]);
        hh[j] = __floats2half2_rn(f0*fa.x + f1*fc.x, f0*fa.y + f1*fc.y);
    }

    __half* dst = g_att + ((size_t)(b*SEQ + qt*QT + qrow))*D_MODEL + h*HDIM + cs;
    *(uint4*)dst = *(const uint4*)hh;
}

// ---------------------------------------------------------------------------
// Launch
// ---------------------------------------------------------------------------
extern "C" void kernel_launch(void* const* d_in, const int* in_sizes, int n_in,
                              void* d_out, int out_size)
{
    (void)in_sizes; (void)n_in; (void)out_size;
    const float* x  = (const float*)d_in[0];
    const float* ck = (const float*)d_in[1];
    const float* cv = (const float*)d_in[2];
    const float* wq = (const float*)d_in[3];
    const float* bq = (const float*)d_in[4];
    const float* wk = (const float*)d_in[5];
    const float* bk = (const float*)d_in[6];
    const float* wv = (const float*)d_in[7];
    const float* bv = (const float*)d_in[8];
    const float* wo = (const float*)d_in[9];
    const float* bo = (const float*)d_in[10];
    float* out = (float*)d_out;

    __half *pxh, *pq, *pk, *pv, *pa, *pckh, *pcvh, *pw;
    cudaGetSymbolAddress((void**)&pxh,  g_xh);
    cudaGetSymbolAddress((void**)&pq,   g_q);
    cudaGetSymbolAddress((void**)&pk,   g_k);
    cudaGetSymbolAddress((void**)&pv,   g_v);
    cudaGetSymbolAddress((void**)&pa,   g_att);
    cudaGetSymbolAddress((void**)&pckh, g_ck);
    cudaGetSymbolAddress((void**)&pcvh, g_cv);
    cudaGetSymbolAddress((void**)&pw,   g_wt);

    __half* wt_o = pw + 3*(size_t)D_MODEL*D_MODEL;

    cudaFuncSetAttribute(gemm_qkv, cudaFuncAttributeMaxDynamicSharedMemorySize, GEMM_DSMEM);
    cudaFuncSetAttribute(gemm_o,   cudaFuncAttributeMaxDynamicSharedMemorySize, GEMM_DSMEM);
    cudaFuncSetAttribute(attn_h,   cudaFuncAttributeMaxDynamicSharedMemorySize, ATTN_SMEM_H);

    // Fused prep (converts + all four weight transposes) in one launch
    prep_all<<<dim3(MROWS*D_MODEL/8/256, 7), 256>>>(
        x, ck, cv, wq, wk, wv, wo, pxh, pckh, pcvh, pw);

    // Fused QKV projection (Q pre-scaled by sc*log2(e) in fp32 epilogue)
    gemm_qkv<<<dim3(3*D_MODEL/GBN, MROWS/GBM), 256, GEMM_DSMEM>>>(
        pxh, pw, bq, bk, bv, pq, pk, pv);

    // Attention: split-KV + combine
    dim3 ag(NQT*2, NHEAD, BATCH);
    attn_h<<<ag, 128, ATTN_SMEM_H>>>();
    attn_combine<<<(BATCH*NHEAD*NQT*QT)/16, 256>>>();

    // Output projection (fp32 out)
    gemm_o<<<dim3(D_MODEL/GBN, MROWS/GBM), 256, GEMM_DSMEM>>>(pa, wt_o, bo, out);
}